// round 11
// baseline (speedup 1.0000x reference)
#include <cuda_runtime.h>
#include <cuda_bf16.h>
#include <math.h>
#include <stdint.h>

// ---------------------------------------------------------------------------
// BondLengthHead, fully tensorized (mma.sync bf16 split, f32 accum):
//   P = z @ W1[0:128,:], Q = z @ W1[128:256,:]   (node_mma_kernel, HMMA)
//   C = embed @ W1[256:288,:] + b1               (13x128)
//   edge kernel: warp-autonomous 32-edge pipelines (2 m16-tiles per warp),
//   no CTA barriers in loop:
//     g = relu(P[src]+Q[dst]+C[bt]) -> split bf16 hi/lo
//     D = Ahi Bhi + Ahi Blo + Alo Bhi  (m16n8k16 HMMA, f32 acc)
//     out = softplus(relu(D + b2) . W3 + b3)
// NOTE: harness compiles via compute_103 (no 'a') -> no tcgen05/TMEM allowed.
// ---------------------------------------------------------------------------

#define MAXN 100000

__device__ float g_PQ[(size_t)MAXN * 256];
__device__ float g_C[13 * 128];
__device__ int   g_ei_is64;
__device__ int   g_bt_is64;

__device__ __forceinline__ uint32_t smem_u32(const void* p) {
    uint32_t a;
    asm("{ .reg .u64 t; cvta.to.shared.u64 t, %1; cvt.u32.u64 %0, t; }"
        : "=r"(a) : "l"(p));
    return a;
}

__device__ __forceinline__ void ldsm_x4(uint32_t* r, uint32_t addr) {
    asm volatile("ldmatrix.sync.aligned.m8n8.x4.shared.b16 {%0,%1,%2,%3}, [%4];"
                 : "=r"(r[0]), "=r"(r[1]), "=r"(r[2]), "=r"(r[3]) : "r"(addr));
}

__device__ __forceinline__ void mma_bf16(float* d, const uint32_t* a,
                                         uint32_t b0, uint32_t b1) {
    asm volatile("mma.sync.aligned.m16n8k16.row.col.f32.bf16.bf16.f32 "
                 "{%0,%1,%2,%3}, {%4,%5,%6,%7}, {%8,%9}, {%0,%1,%2,%3};"
                 : "+f"(d[0]), "+f"(d[1]), "+f"(d[2]), "+f"(d[3])
                 : "r"(a[0]), "r"(a[1]), "r"(a[2]), "r"(a[3]),
                   "r"(b0), "r"(b1));
}

__device__ __forceinline__ float softplus_f(float x) {
    return fmaxf(x, 0.0f) + log1pf(expf(-fabsf(x)));
}

// ===========================================================================
__global__ void detect_dtype_kernel(const int* __restrict__ ei,
                                    const int* __restrict__ bt) {
    if (threadIdx.x == 0 && blockIdx.x == 0) {
        int e64 = 1, b64 = 1;
        #pragma unroll 1
        for (int i = 0; i < 64; i++) if (ei[2 * i + 1] != 0) { e64 = 0; break; }
        #pragma unroll 1
        for (int i = 0; i < 64; i++) if (bt[2 * i + 1] != 0) { b64 = 0; break; }
        g_ei_is64 = e64;
        g_bt_is64 = b64;
    }
}

__global__ void cemb_kernel(const float* __restrict__ embed,
                            const float* __restrict__ W1,
                            const float* __restrict__ b1) {
    int idx = blockIdx.x * 256 + threadIdx.x;
    if (idx < 13 * 128) {
        int t = idx >> 7, j = idx & 127;
        float s = b1[j];
        #pragma unroll
        for (int k = 0; k < 32; k++)
            s = fmaf(embed[t * 32 + k], W1[(256 + k) * 128 + j], s);
        g_C[idx] = s;
    }
}

// ===========================================================================
// Node GEMM on mma.sync (unchanged from R5 pass)
// ===========================================================================
#define NROWB 272
#define NOFF_AHI 0
#define NOFF_ALO (64 * NROWB)
#define NOFF_WHI (2 * 64 * NROWB)
#define NOFF_WLO (2 * 64 * NROWB + 128 * NROWB)
#define NODE_SMEM (2 * 64 * NROWB + 2 * 128 * NROWB)

__global__ void __launch_bounds__(256, 2)
node_mma_kernel(const float* __restrict__ z,
                const float* __restrict__ W1,
                int nNodes, int nTilesN)
{
    extern __shared__ char sb[];
    const uint32_t base = smem_u32(sb);
    char* Ahi = sb + NOFF_AHI;
    char* Alo = sb + NOFF_ALO;
    char* Whi = sb + NOFF_WHI;
    char* Wlo = sb + NOFF_WLO;

    const int tid  = threadIdx.x;
    const int wid  = tid >> 5;
    const int lane = tid & 31;
    const int g    = lane >> 2;
    const int tg   = lane & 3;

    const int halfStride = gridDim.x >> 1;
    const int half = (blockIdx.x >= halfStride) ? 1 : 0;
    const int t0   = blockIdx.x - half * halfStride;
    const int krow = half * 128;

    for (int i = tid; i < 128 * 128; i += 256) {
        int k = i >> 7, n = i & 127;
        float w = W1[(krow + k) * 128 + n];
        __nv_bfloat16 hi = __float2bfloat16(w);
        float lof = w - __bfloat162float(hi);
        uint32_t off = (uint32_t)n * NROWB + (uint32_t)k * 2;
        *(__nv_bfloat16*)(Whi + off) = hi;
        *(__nv_bfloat16*)(Wlo + off) = __float2bfloat16(lof);
    }

    const uint32_t rowoff = (uint32_t)(((lane & 7) + ((lane & 8) ? 8 : 0)) * NROWB
                                       + ((lane & 16) ? 16 : 0));
    const int mt = wid & 3;
    const int ng = (wid >> 2) * 64;
    const uint32_t aHiB = base + NOFF_AHI + (uint32_t)(mt * 16) * NROWB + rowoff;
    const uint32_t aLoB = base + NOFF_ALO + (uint32_t)(mt * 16) * NROWB + rowoff;
    const uint32_t wHiB = base + NOFF_WHI + (uint32_t)ng * NROWB + rowoff;
    const uint32_t wLoB = base + NOFF_WLO + (uint32_t)ng * NROWB + rowoff;

    const float4* z4 = (const float4*)z;

    for (int t = t0; t < nTilesN; t += halfStride) {
        const int nb = t * 64;
        __syncthreads();

        #pragma unroll 2
        for (int idx = tid; idx < 64 * 32; idx += 256) {
            int e = idx >> 5, c = idx & 31;
            float4 v = make_float4(0.f, 0.f, 0.f, 0.f);
            if (nb + e < nNodes) v = z4[(size_t)(nb + e) * 32 + c];
            union { uint2 u; __nv_bfloat16 h[4]; } ph, pl;
            ph.h[0] = __float2bfloat16(v.x);
            ph.h[1] = __float2bfloat16(v.y);
            ph.h[2] = __float2bfloat16(v.z);
            ph.h[3] = __float2bfloat16(v.w);
            pl.h[0] = __float2bfloat16(v.x - __bfloat162float(ph.h[0]));
            pl.h[1] = __float2bfloat16(v.y - __bfloat162float(ph.h[1]));
            pl.h[2] = __float2bfloat16(v.z - __bfloat162float(ph.h[2]));
            pl.h[3] = __float2bfloat16(v.w - __bfloat162float(ph.h[3]));
            uint32_t off = (uint32_t)e * NROWB + (uint32_t)c * 8;
            *(uint2*)(Ahi + off) = ph.u;
            *(uint2*)(Alo + off) = pl.u;
        }
        __syncthreads();

        float D[8][4];
        #pragma unroll
        for (int i = 0; i < 8; i++)
            #pragma unroll
            for (int j = 0; j < 4; j++) D[i][j] = 0.f;

        #pragma unroll
        for (int ks = 0; ks < 8; ks++) {
            uint32_t ah[4], al[4];
            ldsm_x4(ah, aHiB + ks * 32);
            ldsm_x4(al, aLoB + ks * 32);
            #pragma unroll
            for (int p = 0; p < 4; p++) {
                uint32_t bh[4], bl[4];
                ldsm_x4(bh, wHiB + (uint32_t)(p * 16) * NROWB + ks * 32);
                ldsm_x4(bl, wLoB + (uint32_t)(p * 16) * NROWB + ks * 32);
                mma_bf16(D[2 * p],     ah, bh[0], bh[2]);
                mma_bf16(D[2 * p],     ah, bl[0], bl[2]);
                mma_bf16(D[2 * p],     al, bh[0], bh[2]);
                mma_bf16(D[2 * p + 1], ah, bh[1], bh[3]);
                mma_bf16(D[2 * p + 1], ah, bl[1], bl[3]);
                mma_bf16(D[2 * p + 1], al, bh[1], bh[3]);
            }
        }

        {
            int node0 = nb + mt * 16 + g;
            int cbase = half * 128 + ng + tg * 2;
            if (node0 < nNodes) {
                float* r = &g_PQ[(size_t)node0 * 256 + cbase];
                #pragma unroll
                for (int j = 0; j < 8; j++)
                    *(float2*)(r + j * 8) = make_float2(D[j][0], D[j][1]);
            }
            int node1 = node0 + 8;
            if (node1 < nNodes) {
                float* r = &g_PQ[(size_t)node1 * 256 + cbase];
                #pragma unroll
                for (int j = 0; j < 8; j++)
                    *(float2*)(r + j * 8) = make_float2(D[j][2], D[j][3]);
            }
        }
    }
}

// ===========================================================================
// Edge kernel: 4 warps, each owns 32 edges (2 m16-tiles) -> W2 LDSM halved
// ===========================================================================
#define ETILE  128
#define ROWB   272
#define OFF_AHI  0
#define OFF_ALO  (OFF_AHI + 128 * ROWB)
#define OFF_WHI  (OFF_ALO + 128 * ROWB)
#define OFF_WLO  (OFF_WHI + 64 * ROWB)
#define OFF_C    (OFF_WLO + 64 * ROWB)
#define OFF_BW   (OFF_C + 13 * 128 * 4)
#define EDGE_SMEM (OFF_BW + 64 * 8)

__global__ void __launch_bounds__(128, 2)
edge_mma_kernel(const void*  __restrict__ eiv,
                const void*  __restrict__ btv,
                const float* __restrict__ W2,
                const float* __restrict__ b2,
                const float* __restrict__ W3,
                const float* __restrict__ b3,
                float* __restrict__ out,
                int E, int nTiles)
{
    extern __shared__ char sb[];
    const uint32_t base = smem_u32(sb);

    char*   Ahi = sb + OFF_AHI;
    char*   Alo = sb + OFF_ALO;
    char*   Whi = sb + OFF_WHI;
    char*   Wlo = sb + OFF_WLO;
    float*  sC  = (float*)(sb + OFF_C);
    float2* sBW = (float2*)(sb + OFF_BW);

    const int tid  = threadIdx.x;
    const int wid  = tid >> 5;
    const int lane = tid & 31;
    const int g    = lane >> 2;
    const int tg   = lane & 3;
    const int ei64 = g_ei_is64, bt64 = g_bt_is64;

    // ---- one-time staging ----
    for (int i = tid; i < 13 * 32; i += 128)
        ((float4*)sC)[i] = ((const float4*)g_C)[i];
    if (tid < 64) sBW[tid] = make_float2(b2[tid], W3[tid]);
    for (int i = tid; i < 128 * 64; i += 128) {
        int k = i >> 6, n = i & 63;
        float w = W2[i];
        __nv_bfloat16 hi = __float2bfloat16(w);
        float lof = w - __bfloat162float(hi);
        uint32_t off = (uint32_t)n * ROWB + (uint32_t)k * 2;
        *(__nv_bfloat16*)(Whi + off) = hi;
        *(__nv_bfloat16*)(Wlo + off) = __float2bfloat16(lof);
    }
    __syncthreads();

    const float b3v = __ldg(b3);

    const uint32_t rowoff = (uint32_t)(((lane & 7) + ((lane & 8) ? 8 : 0)) * ROWB
                                       + ((lane & 16) ? 16 : 0));
    // warp owns rows wid*32 .. wid*32+31 (two m16 tiles)
    const uint32_t aHi0 = base + OFF_AHI + (uint32_t)(wid * 32) * ROWB + rowoff;
    const uint32_t aLo0 = base + OFF_ALO + (uint32_t)(wid * 32) * ROWB + rowoff;
    const uint32_t aHi1 = aHi0 + 16u * ROWB;
    const uint32_t aLo1 = aLo0 + 16u * ROWB;
    const uint32_t wHiBase = base + OFF_WHI + rowoff;
    const uint32_t wLoBase = base + OFF_WLO + rowoff;

    const float4* PQ4 = (const float4*)g_PQ;
    const float4* sC4 = (const float4*)sC;

    for (int tile = blockIdx.x; tile < nTiles; tile += gridDim.x) {
        const int eW = tile * ETILE + wid * 32;   // this warp's 32 edges

        // ---- indices into registers: lane e -> src/dst/bt of edge eW+lane ----
        int rs, rd, rb;
        {
            int e = eW + lane;
            bool valid = e < E;
            if (ei64) {
                const long long* p = (const long long*)eiv;
                rs = valid ? (int)p[e] : 0;
                rd = valid ? (int)p[(size_t)E + e] : 0;
            } else {
                const int* p = (const int*)eiv;
                rs = valid ? p[e] : 0;
                rd = valid ? p[(size_t)E + e] : 0;
            }
            rb = valid ? (bt64 ? (int)((const long long*)btv)[e]
                               : ((const int*)btv)[e]) : 0;
        }
        __syncwarp();

        // ---- gather + relu + split into this warp's private 32 A rows ----
        #pragma unroll 8
        for (int i = 0; i < 32; i++) {
            int s = __shfl_sync(0xffffffffu, rs, i);
            int d = __shfl_sync(0xffffffffu, rd, i);
            int b = __shfl_sync(0xffffffffu, rb, i);
            float4 p  = PQ4[(size_t)s * 64 + lane];
            float4 q  = PQ4[(size_t)d * 64 + 32 + lane];
            float4 cc = sC4[b * 32 + lane];
            float g0 = fmaxf(p.x + q.x + cc.x, 0.f);
            float g1 = fmaxf(p.y + q.y + cc.y, 0.f);
            float g2 = fmaxf(p.z + q.z + cc.z, 0.f);
            float g3 = fmaxf(p.w + q.w + cc.w, 0.f);
            union { uint2 u; __nv_bfloat16 h[4]; } ph, pl;
            ph.h[0] = __float2bfloat16(g0);
            ph.h[1] = __float2bfloat16(g1);
            ph.h[2] = __float2bfloat16(g2);
            ph.h[3] = __float2bfloat16(g3);
            pl.h[0] = __float2bfloat16(g0 - __bfloat162float(ph.h[0]));
            pl.h[1] = __float2bfloat16(g1 - __bfloat162float(ph.h[1]));
            pl.h[2] = __float2bfloat16(g2 - __bfloat162float(ph.h[2]));
            pl.h[3] = __float2bfloat16(g3 - __bfloat162float(ph.h[3]));
            uint32_t off = (uint32_t)(wid * 32 + i) * ROWB + (uint32_t)lane * 8;
            *(uint2*)(Ahi + off) = ph.u;
            *(uint2*)(Alo + off) = pl.u;
        }
        __syncwarp();

        // ---- layer 2 MMAs: 32 edges x 64 n, k=128, 3-term split ----
        float D0[8][4], D1[8][4];
        #pragma unroll
        for (int i = 0; i < 8; i++)
            #pragma unroll
            for (int j = 0; j < 4; j++) { D0[i][j] = 0.f; D1[i][j] = 0.f; }

        #pragma unroll
        for (int ks = 0; ks < 8; ks++) {
            uint32_t ah0[4], al0[4], ah1[4], al1[4];
            ldsm_x4(ah0, aHi0 + ks * 32);
            ldsm_x4(al0, aLo0 + ks * 32);
            ldsm_x4(ah1, aHi1 + ks * 32);
            ldsm_x4(al1, aLo1 + ks * 32);
            #pragma unroll
            for (int p = 0; p < 4; p++) {
                uint32_t bh[4], bl[4];
                ldsm_x4(bh, wHiBase + (uint32_t)(p * 16) * ROWB + ks * 32);
                ldsm_x4(bl, wLoBase + (uint32_t)(p * 16) * ROWB + ks * 32);
                mma_bf16(D0[2 * p],     ah0, bh[0], bh[2]);
                mma_bf16(D0[2 * p],     ah0, bl[0], bl[2]);
                mma_bf16(D0[2 * p],     al0, bh[0], bh[2]);
                mma_bf16(D0[2 * p + 1], ah0, bh[1], bh[3]);
                mma_bf16(D0[2 * p + 1], ah0, bl[1], bl[3]);
                mma_bf16(D0[2 * p + 1], al0, bh[1], bh[3]);
                mma_bf16(D1[2 * p],     ah1, bh[0], bh[2]);
                mma_bf16(D1[2 * p],     ah1, bl[0], bl[2]);
                mma_bf16(D1[2 * p],     al1, bh[0], bh[2]);
                mma_bf16(D1[2 * p + 1], ah1, bh[1], bh[3]);
                mma_bf16(D1[2 * p + 1], ah1, bl[1], bl[3]);
                mma_bf16(D1[2 * p + 1], al1, bh[1], bh[3]);
            }
        }

        // ---- layer 3 + softplus, per m-tile ----
        #pragma unroll
        for (int mt = 0; mt < 2; mt++) {
            float (*D)[4] = (mt == 0) ? D0 : D1;
            float p0 = 0.f, p1 = 0.f;
            #pragma unroll
            for (int nt = 0; nt < 8; nt++) {
                int n = nt * 8 + tg * 2;
                float2 bw0 = sBW[n];
                float2 bw1 = sBW[n + 1];
                p0 = fmaf(fmaxf(D[nt][0] + bw0.x, 0.f), bw0.y, p0);
                p0 = fmaf(fmaxf(D[nt][1] + bw1.x, 0.f), bw1.y, p0);
                p1 = fmaf(fmaxf(D[nt][2] + bw0.x, 0.f), bw0.y, p1);
                p1 = fmaf(fmaxf(D[nt][3] + bw1.x, 0.f), bw1.y, p1);
            }
            p0 += __shfl_xor_sync(0xffffffffu, p0, 1);
            p0 += __shfl_xor_sync(0xffffffffu, p0, 2);
            p1 += __shfl_xor_sync(0xffffffffu, p1, 1);
            p1 += __shfl_xor_sync(0xffffffffu, p1, 2);
            if (tg == 0) {
                int e0 = eW + mt * 16 + g;
                if (e0 < E)     out[e0]     = softplus_f(p0 + b3v);
                if (e0 + 8 < E) out[e0 + 8] = softplus_f(p1 + b3v);
            }
        }
        // next iteration's __syncwarp orders A reuse; warp-private rows only
    }
}

// ===========================================================================
extern "C" void kernel_launch(void* const* d_in, const int* in_sizes, int n_in,
                              void* d_out, int out_size)
{
    const float* z     = (const float*)d_in[0];
    const void*  ei    = d_in[1];
    const void*  bt    = d_in[2];
    const float* embed = (const float*)d_in[3];
    const float* W1    = (const float*)d_in[4];
    const float* b1    = (const float*)d_in[5];
    const float* W2    = (const float*)d_in[6];
    const float* b2    = (const float*)d_in[7];
    const float* W3    = (const float*)d_in[8];
    const float* b3    = (const float*)d_in[9];
    float* out = (float*)d_out;

    int nNodes = in_sizes[0] / 128;
    int E = out_size;
    int nTiles  = (E + ETILE - 1) / ETILE;
    int nTilesN = (nNodes + 63) / 64;

    static int attr_done = 0;
    if (!attr_done) {
        cudaFuncSetAttribute(node_mma_kernel,
                             cudaFuncAttributeMaxDynamicSharedMemorySize, NODE_SMEM);
        cudaFuncSetAttribute(edge_mma_kernel,
                             cudaFuncAttributeMaxDynamicSharedMemorySize, EDGE_SMEM);
        attr_done = 1;
    }

    detect_dtype_kernel<<<1, 32>>>((const int*)ei, (const int*)bt);
    cemb_kernel<<<7, 256>>>(embed, W1, b1);

    node_mma_kernel<<<296, 256, NODE_SMEM>>>(z, W1, nNodes, nTilesN);

    int eg = nTiles < 296 ? nTiles : 296;
    edge_mma_kernel<<<eg, 128, EDGE_SMEM>>>(ei, bt, W2, b2, W3, b3, out, E, nTiles);
}

// round 12
// speedup vs baseline: 1.2988x; 1.2988x over previous
#include <cuda_runtime.h>
#include <cuda_bf16.h>
#include <math.h>
#include <stdint.h>

// ---------------------------------------------------------------------------
// BondLengthHead, fully tensorized (mma.sync bf16 split, f32 accum):
//   P = z @ W1[0:128,:], Q = z @ W1[128:256,:]   (node_mma_kernel, HMMA)
//   C = embed @ W1[256:288,:] + b1               (13x128)
//   edge kernel: warp-PAIR pipelines: pair owns 32 edges, each warp one n-half
//   (halves W2 ldmatrix traffic at unchanged warp count):
//     g = relu(P[src]+Q[dst]+C[bt]) -> split bf16 hi/lo
//     D = Ahi Bhi + Ahi Blo + Alo Bhi  (m16n8k16 HMMA, f32 acc)
//     out = softplus(relu(D + b2) . W3 + b3)
// NOTE: harness compiles via compute_103 (no 'a') -> no tcgen05/TMEM allowed.
// ---------------------------------------------------------------------------

#define MAXN 100000

__device__ float g_PQ[(size_t)MAXN * 256];
__device__ float g_C[13 * 128];
__device__ int   g_ei_is64;
__device__ int   g_bt_is64;

__device__ __forceinline__ uint32_t smem_u32(const void* p) {
    uint32_t a;
    asm("{ .reg .u64 t; cvta.to.shared.u64 t, %1; cvt.u32.u64 %0, t; }"
        : "=r"(a) : "l"(p));
    return a;
}

__device__ __forceinline__ void ldsm_x4(uint32_t* r, uint32_t addr) {
    asm volatile("ldmatrix.sync.aligned.m8n8.x4.shared.b16 {%0,%1,%2,%3}, [%4];"
                 : "=r"(r[0]), "=r"(r[1]), "=r"(r[2]), "=r"(r[3]) : "r"(addr));
}

__device__ __forceinline__ void mma_bf16(float* d, const uint32_t* a,
                                         uint32_t b0, uint32_t b1) {
    asm volatile("mma.sync.aligned.m16n8k16.row.col.f32.bf16.bf16.f32 "
                 "{%0,%1,%2,%3}, {%4,%5,%6,%7}, {%8,%9}, {%0,%1,%2,%3};"
                 : "+f"(d[0]), "+f"(d[1]), "+f"(d[2]), "+f"(d[3])
                 : "r"(a[0]), "r"(a[1]), "r"(a[2]), "r"(a[3]),
                   "r"(b0), "r"(b1));
}

__device__ __forceinline__ float softplus_f(float x) {
    return fmaxf(x, 0.0f) + log1pf(expf(-fabsf(x)));
}

// ===========================================================================
__global__ void detect_dtype_kernel(const int* __restrict__ ei,
                                    const int* __restrict__ bt) {
    if (threadIdx.x == 0 && blockIdx.x == 0) {
        int e64 = 1, b64 = 1;
        #pragma unroll 1
        for (int i = 0; i < 64; i++) if (ei[2 * i + 1] != 0) { e64 = 0; break; }
        #pragma unroll 1
        for (int i = 0; i < 64; i++) if (bt[2 * i + 1] != 0) { b64 = 0; break; }
        g_ei_is64 = e64;
        g_bt_is64 = b64;
    }
}

__global__ void cemb_kernel(const float* __restrict__ embed,
                            const float* __restrict__ W1,
                            const float* __restrict__ b1) {
    int idx = blockIdx.x * 256 + threadIdx.x;
    if (idx < 13 * 128) {
        int t = idx >> 7, j = idx & 127;
        float s = b1[j];
        #pragma unroll
        for (int k = 0; k < 32; k++)
            s = fmaf(embed[t * 32 + k], W1[(256 + k) * 128 + j], s);
        g_C[idx] = s;
    }
}

// ===========================================================================
// Node GEMM on mma.sync (unchanged from R5 pass)
// ===========================================================================
#define NROWB 272
#define NOFF_AHI 0
#define NOFF_ALO (64 * NROWB)
#define NOFF_WHI (2 * 64 * NROWB)
#define NOFF_WLO (2 * 64 * NROWB + 128 * NROWB)
#define NODE_SMEM (2 * 64 * NROWB + 2 * 128 * NROWB)

__global__ void __launch_bounds__(256, 2)
node_mma_kernel(const float* __restrict__ z,
                const float* __restrict__ W1,
                int nNodes, int nTilesN)
{
    extern __shared__ char sb[];
    const uint32_t base = smem_u32(sb);
    char* Ahi = sb + NOFF_AHI;
    char* Alo = sb + NOFF_ALO;
    char* Whi = sb + NOFF_WHI;
    char* Wlo = sb + NOFF_WLO;

    const int tid  = threadIdx.x;
    const int wid  = tid >> 5;
    const int lane = tid & 31;
    const int g    = lane >> 2;
    const int tg   = lane & 3;

    const int halfStride = gridDim.x >> 1;
    const int half = (blockIdx.x >= halfStride) ? 1 : 0;
    const int t0   = blockIdx.x - half * halfStride;
    const int krow = half * 128;

    for (int i = tid; i < 128 * 128; i += 256) {
        int k = i >> 7, n = i & 127;
        float w = W1[(krow + k) * 128 + n];
        __nv_bfloat16 hi = __float2bfloat16(w);
        float lof = w - __bfloat162float(hi);
        uint32_t off = (uint32_t)n * NROWB + (uint32_t)k * 2;
        *(__nv_bfloat16*)(Whi + off) = hi;
        *(__nv_bfloat16*)(Wlo + off) = __float2bfloat16(lof);
    }

    const uint32_t rowoff = (uint32_t)(((lane & 7) + ((lane & 8) ? 8 : 0)) * NROWB
                                       + ((lane & 16) ? 16 : 0));
    const int mt = wid & 3;
    const int ng = (wid >> 2) * 64;
    const uint32_t aHiB = base + NOFF_AHI + (uint32_t)(mt * 16) * NROWB + rowoff;
    const uint32_t aLoB = base + NOFF_ALO + (uint32_t)(mt * 16) * NROWB + rowoff;
    const uint32_t wHiB = base + NOFF_WHI + (uint32_t)ng * NROWB + rowoff;
    const uint32_t wLoB = base + NOFF_WLO + (uint32_t)ng * NROWB + rowoff;

    const float4* z4 = (const float4*)z;

    for (int t = t0; t < nTilesN; t += halfStride) {
        const int nb = t * 64;
        __syncthreads();

        #pragma unroll 2
        for (int idx = tid; idx < 64 * 32; idx += 256) {
            int e = idx >> 5, c = idx & 31;
            float4 v = make_float4(0.f, 0.f, 0.f, 0.f);
            if (nb + e < nNodes) v = z4[(size_t)(nb + e) * 32 + c];
            union { uint2 u; __nv_bfloat16 h[4]; } ph, pl;
            ph.h[0] = __float2bfloat16(v.x);
            ph.h[1] = __float2bfloat16(v.y);
            ph.h[2] = __float2bfloat16(v.z);
            ph.h[3] = __float2bfloat16(v.w);
            pl.h[0] = __float2bfloat16(v.x - __bfloat162float(ph.h[0]));
            pl.h[1] = __float2bfloat16(v.y - __bfloat162float(ph.h[1]));
            pl.h[2] = __float2bfloat16(v.z - __bfloat162float(ph.h[2]));
            pl.h[3] = __float2bfloat16(v.w - __bfloat162float(ph.h[3]));
            uint32_t off = (uint32_t)e * NROWB + (uint32_t)c * 8;
            *(uint2*)(Ahi + off) = ph.u;
            *(uint2*)(Alo + off) = pl.u;
        }
        __syncthreads();

        float D[8][4];
        #pragma unroll
        for (int i = 0; i < 8; i++)
            #pragma unroll
            for (int j = 0; j < 4; j++) D[i][j] = 0.f;

        #pragma unroll
        for (int ks = 0; ks < 8; ks++) {
            uint32_t ah[4], al[4];
            ldsm_x4(ah, aHiB + ks * 32);
            ldsm_x4(al, aLoB + ks * 32);
            #pragma unroll
            for (int p = 0; p < 4; p++) {
                uint32_t bh[4], bl[4];
                ldsm_x4(bh, wHiB + (uint32_t)(p * 16) * NROWB + ks * 32);
                ldsm_x4(bl, wLoB + (uint32_t)(p * 16) * NROWB + ks * 32);
                mma_bf16(D[2 * p],     ah, bh[0], bh[2]);
                mma_bf16(D[2 * p],     ah, bl[0], bl[2]);
                mma_bf16(D[2 * p],     al, bh[0], bh[2]);
                mma_bf16(D[2 * p + 1], ah, bh[1], bh[3]);
                mma_bf16(D[2 * p + 1], ah, bl[1], bl[3]);
                mma_bf16(D[2 * p + 1], al, bh[1], bh[3]);
            }
        }

        {
            int node0 = nb + mt * 16 + g;
            int cbase = half * 128 + ng + tg * 2;
            if (node0 < nNodes) {
                float* r = &g_PQ[(size_t)node0 * 256 + cbase];
                #pragma unroll
                for (int j = 0; j < 8; j++)
                    *(float2*)(r + j * 8) = make_float2(D[j][0], D[j][1]);
            }
            int node1 = node0 + 8;
            if (node1 < nNodes) {
                float* r = &g_PQ[(size_t)node1 * 256 + cbase];
                #pragma unroll
                for (int j = 0; j < 8; j++)
                    *(float2*)(r + j * 8) = make_float2(D[j][2], D[j][3]);
            }
        }
    }
}

// ===========================================================================
// Edge kernel: 8 warps in 4 pairs; pair owns 32 edges, warp owns one n-half
// ===========================================================================
#define ETILE  128
#define ROWB   272
#define OFF_AHI  0
#define OFF_ALO  (OFF_AHI + 128 * ROWB)
#define OFF_WHI  (OFF_ALO + 128 * ROWB)
#define OFF_WLO  (OFF_WHI + 64 * ROWB)
#define OFF_C    (OFF_WLO + 64 * ROWB)
#define OFF_BW   (OFF_C + 13 * 128 * 4)
#define OFF_PART (OFF_BW + 64 * 8)
#define EDGE_SMEM (OFF_PART + 128 * 4)

__global__ void __launch_bounds__(256, 2)
edge_mma_kernel(const void*  __restrict__ eiv,
                const void*  __restrict__ btv,
                const float* __restrict__ W2,
                const float* __restrict__ b2,
                const float* __restrict__ W3,
                const float* __restrict__ b3,
                float* __restrict__ out,
                int E, int nTiles)
{
    extern __shared__ char sb[];
    const uint32_t base = smem_u32(sb);

    char*   Ahi = sb + OFF_AHI;
    char*   Alo = sb + OFF_ALO;
    char*   Whi = sb + OFF_WHI;
    char*   Wlo = sb + OFF_WLO;
    float*  sC  = (float*)(sb + OFF_C);
    float2* sBW = (float2*)(sb + OFF_BW);
    float*  sPart = (float*)(sb + OFF_PART);

    const int tid  = threadIdx.x;
    const int wid  = tid >> 5;
    const int lane = tid & 31;
    const int g    = lane >> 2;
    const int tg   = lane & 3;
    const int pair = wid >> 1;          // 0..3: owns edges pair*32..+31
    const int sub  = wid & 1;           // n-half: sub*32..+31
    const int ei64 = g_ei_is64, bt64 = g_bt_is64;

    // ---- one-time staging ----
    for (int i = tid; i < 13 * 32; i += 256)
        ((float4*)sC)[i] = ((const float4*)g_C)[i];
    if (tid < 64) sBW[tid] = make_float2(b2[tid], W3[tid]);
    for (int i = tid; i < 128 * 64; i += 256) {
        int k = i >> 6, n = i & 63;
        float w = W2[i];
        __nv_bfloat16 hi = __float2bfloat16(w);
        float lof = w - __bfloat162float(hi);
        uint32_t off = (uint32_t)n * ROWB + (uint32_t)k * 2;
        *(__nv_bfloat16*)(Whi + off) = hi;
        *(__nv_bfloat16*)(Wlo + off) = __float2bfloat16(lof);
    }
    __syncthreads();

    const float b3v = __ldg(b3);

    const uint32_t rowoff = (uint32_t)(((lane & 7) + ((lane & 8) ? 8 : 0)) * ROWB
                                       + ((lane & 16) ? 16 : 0));
    // pair's A rows: pair*32 .. +31 (two m16 tiles)
    const uint32_t aHi0 = base + OFF_AHI + (uint32_t)(pair * 32) * ROWB + rowoff;
    const uint32_t aLo0 = base + OFF_ALO + (uint32_t)(pair * 32) * ROWB + rowoff;
    const uint32_t aHi1 = aHi0 + 16u * ROWB;
    const uint32_t aLo1 = aLo0 + 16u * ROWB;
    // warp's W rows: n = sub*32 .. +31
    const uint32_t wHiBase = base + OFF_WHI + (uint32_t)(sub * 32) * ROWB + rowoff;
    const uint32_t wLoBase = base + OFF_WLO + (uint32_t)(sub * 32) * ROWB + rowoff;

    const float4* PQ4 = (const float4*)g_PQ;
    const float4* sC4 = (const float4*)sC;
    const int laneSel = lane & 15;
    const int barid = 1 + pair;

    for (int tile = blockIdx.x; tile < nTiles; tile += gridDim.x) {
        const int ePair = tile * ETILE + pair * 32;   // pair's 32 edges
        const int eW    = ePair + sub * 16;           // this warp gathers these 16

        // ---- indices: lanes 0..15 src, 16..31 dst of the warp's 16 edges ----
        int rs, rbt = 0;
        {
            int e = eW + laneSel;
            bool valid = e < E;
            size_t half = (lane < 16) ? 0 : (size_t)E;
            if (ei64) {
                const long long* p = (const long long*)eiv;
                rs = valid ? (int)p[half + e] : 0;
            } else {
                const int* p = (const int*)eiv;
                rs = valid ? p[half + e] : 0;
            }
            if (lane < 16) {
                rbt = valid ? (bt64 ? (int)((const long long*)btv)[e]
                                    : ((const int*)btv)[e]) : 0;
            }
        }
        __syncwarp();

        // ---- gather + relu + split into A rows (pair*32 + sub*16 + i) ----
        #pragma unroll
        for (int i = 0; i < 16; i++) {
            int s = __shfl_sync(0xffffffffu, rs, i);
            int d = __shfl_sync(0xffffffffu, rs, 16 + i);
            int b = __shfl_sync(0xffffffffu, rbt, i);
            float4 p  = PQ4[(size_t)s * 64 + lane];
            float4 q  = PQ4[(size_t)d * 64 + 32 + lane];
            float4 cc = sC4[b * 32 + lane];
            float g0 = fmaxf(p.x + q.x + cc.x, 0.f);
            float g1 = fmaxf(p.y + q.y + cc.y, 0.f);
            float g2 = fmaxf(p.z + q.z + cc.z, 0.f);
            float g3 = fmaxf(p.w + q.w + cc.w, 0.f);
            union { uint2 u; __nv_bfloat16 h[4]; } ph, pl;
            ph.h[0] = __float2bfloat16(g0);
            ph.h[1] = __float2bfloat16(g1);
            ph.h[2] = __float2bfloat16(g2);
            ph.h[3] = __float2bfloat16(g3);
            pl.h[0] = __float2bfloat16(g0 - __bfloat162float(ph.h[0]));
            pl.h[1] = __float2bfloat16(g1 - __bfloat162float(ph.h[1]));
            pl.h[2] = __float2bfloat16(g2 - __bfloat162float(ph.h[2]));
            pl.h[3] = __float2bfloat16(g3 - __bfloat162float(ph.h[3]));
            uint32_t off = (uint32_t)(pair * 32 + sub * 16 + i) * ROWB
                         + (uint32_t)lane * 8;
            *(uint2*)(Ahi + off) = ph.u;
            *(uint2*)(Alo + off) = pl.u;
        }
        // pair barrier: both warps' A rows visible before either reads
        asm volatile("bar.sync %0, 64;" :: "r"(barid) : "memory");

        // ---- layer 2 MMAs: 32 edges x 32 n (this warp's half), k=128 ----
        // D[mt][q][4]: mt = m16 tile, q = n8 tile within the 32-n half
        float D[2][4][4];
        #pragma unroll
        for (int m = 0; m < 2; m++)
            #pragma unroll
            for (int q = 0; q < 4; q++)
                #pragma unroll
                for (int j = 0; j < 4; j++) D[m][q][j] = 0.f;

        #pragma unroll
        for (int ks = 0; ks < 8; ks++) {
            uint32_t ah0[4], al0[4], ah1[4], al1[4];
            ldsm_x4(ah0, aHi0 + ks * 32);
            ldsm_x4(al0, aLo0 + ks * 32);
            ldsm_x4(ah1, aHi1 + ks * 32);
            ldsm_x4(al1, aLo1 + ks * 32);
            #pragma unroll
            for (int p2 = 0; p2 < 2; p2++) {
                uint32_t bh[4], bl[4];
                ldsm_x4(bh, wHiBase + (uint32_t)(p2 * 16) * ROWB + ks * 32);
                ldsm_x4(bl, wLoBase + (uint32_t)(p2 * 16) * ROWB + ks * 32);
                mma_bf16(D[0][2 * p2],     ah0, bh[0], bh[2]);
                mma_bf16(D[0][2 * p2],     ah0, bl[0], bl[2]);
                mma_bf16(D[0][2 * p2],     al0, bh[0], bh[2]);
                mma_bf16(D[0][2 * p2 + 1], ah0, bh[1], bh[3]);
                mma_bf16(D[0][2 * p2 + 1], ah0, bl[1], bl[3]);
                mma_bf16(D[0][2 * p2 + 1], al0, bh[1], bh[3]);
                mma_bf16(D[1][2 * p2],     ah1, bh[0], bh[2]);
                mma_bf16(D[1][2 * p2],     ah1, bl[0], bl[2]);
                mma_bf16(D[1][2 * p2],     al1, bh[0], bh[2]);
                mma_bf16(D[1][2 * p2 + 1], ah1, bh[1], bh[3]);
                mma_bf16(D[1][2 * p2 + 1], ah1, bl[1], bl[3]);
                mma_bf16(D[1][2 * p2 + 1], al1, bh[1], bh[3]);
            }
        }

        // ---- layer 3 partials over this warp's 32 n ----
        // thread's cols: n = sub*32 + q*8... with q->(p2,h): n = sub*32+p2*16+h*8
        float p0[2], p1[2];
        #pragma unroll
        for (int m = 0; m < 2; m++) {
            float a0 = 0.f, a1 = 0.f;
            #pragma unroll
            for (int p2 = 0; p2 < 2; p2++) {
                #pragma unroll
                for (int h = 0; h < 2; h++) {
                    int n = sub * 32 + p2 * 16 + h * 8 + tg * 2;
                    float2 bw0 = sBW[n];
                    float2 bw1 = sBW[n + 1];
                    int q = 2 * p2 + h;
                    a0 = fmaf(fmaxf(D[m][q][0] + bw0.x, 0.f), bw0.y, a0);
                    a0 = fmaf(fmaxf(D[m][q][1] + bw1.x, 0.f), bw1.y, a0);
                    a1 = fmaf(fmaxf(D[m][q][2] + bw0.x, 0.f), bw0.y, a1);
                    a1 = fmaf(fmaxf(D[m][q][3] + bw1.x, 0.f), bw1.y, a1);
                }
            }
            a0 += __shfl_xor_sync(0xffffffffu, a0, 1);
            a0 += __shfl_xor_sync(0xffffffffu, a0, 2);
            a1 += __shfl_xor_sync(0xffffffffu, a1, 1);
            a1 += __shfl_xor_sync(0xffffffffu, a1, 2);
            p0[m] = a0;   // edge ePair + m*16 + g
            p1[m] = a1;   // edge ePair + m*16 + 8 + g
        }

        // ---- cross-warp combine: sub1 writes partials, sub0 finalizes ----
        if (sub == 1 && tg == 0) {
            sPart[pair * 32 + 0 * 16 + g]     = p0[0];
            sPart[pair * 32 + 0 * 16 + 8 + g] = p1[0];
            sPart[pair * 32 + 1 * 16 + g]     = p0[1];
            sPart[pair * 32 + 1 * 16 + 8 + g] = p1[1];
        }
        asm volatile("bar.sync %0, 64;" :: "r"(barid) : "memory");
        if (sub == 0 && tg == 0) {
            #pragma unroll
            for (int m = 0; m < 2; m++) {
                int e0 = ePair + m * 16 + g;
                float t0 = p0[m] + sPart[pair * 32 + m * 16 + g];
                float t1 = p1[m] + sPart[pair * 32 + m * 16 + 8 + g];
                if (e0 < E)     out[e0]     = softplus_f(t0 + b3v);
                if (e0 + 8 < E) out[e0 + 8] = softplus_f(t1 + b3v);
            }
        }
        // the barrier above also orders: both warps finished reading A
        // before the next tile's gather overwrites it.
    }
}

// ===========================================================================
extern "C" void kernel_launch(void* const* d_in, const int* in_sizes, int n_in,
                              void* d_out, int out_size)
{
    const float* z     = (const float*)d_in[0];
    const void*  ei    = d_in[1];
    const void*  bt    = d_in[2];
    const float* embed = (const float*)d_in[3];
    const float* W1    = (const float*)d_in[4];
    const float* b1    = (const float*)d_in[5];
    const float* W2    = (const float*)d_in[6];
    const float* b2    = (const float*)d_in[7];
    const float* W3    = (const float*)d_in[8];
    const float* b3    = (const float*)d_in[9];
    float* out = (float*)d_out;

    int nNodes = in_sizes[0] / 128;
    int E = out_size;
    int nTiles  = (E + ETILE - 1) / ETILE;
    int nTilesN = (nNodes + 63) / 64;

    static int attr_done = 0;
    if (!attr_done) {
        cudaFuncSetAttribute(node_mma_kernel,
                             cudaFuncAttributeMaxDynamicSharedMemorySize, NODE_SMEM);
        cudaFuncSetAttribute(edge_mma_kernel,
                             cudaFuncAttributeMaxDynamicSharedMemorySize, EDGE_SMEM);
        attr_done = 1;
    }

    detect_dtype_kernel<<<1, 32>>>((const int*)ei, (const int*)bt);
    cemb_kernel<<<7, 256>>>(embed, W1, b1);

    node_mma_kernel<<<296, 256, NODE_SMEM>>>(z, W1, nNodes, nTilesN);

    int eg = nTiles < 296 ? nTiles : 296;
    edge_mma_kernel<<<eg, 256, EDGE_SMEM>>>(ei, bt, W2, b2, W3, b3, out, E, nTiles);
}

// round 13
// speedup vs baseline: 1.4856x; 1.1439x over previous
#include <cuda_runtime.h>
#include <cuda_bf16.h>
#include <cuda_fp16.h>
#include <math.h>
#include <stdint.h>

// ---------------------------------------------------------------------------
// BondLengthHead:
//   P = z @ W1[0:128,:], Q = z @ W1[128:256,:]   (node_mma_kernel, bf16 3-term)
//   C = embed @ W1[256:288,:] + b1               (13x128)
//   edge kernel (fp16, warp-autonomous, 3 CTAs/SM):
//     g = relu(P[src]+Q[dst]+C[bt]) -> fp16 A tile (single)
//     W2 split fp16 hi/lo (W effectively exact)
//     D = Ah Wh + Ah Wl  (m16n8k16 HMMA fp16, f32 acc)
//     out = softplus(relu(D + b2) . W3 + b3)
// NOTE: harness compiles via compute_103 (no 'a') -> no tcgen05/TMEM allowed.
// ---------------------------------------------------------------------------

#define MAXN 100000

__device__ float g_PQ[(size_t)MAXN * 256];
__device__ float g_C[13 * 128];
__device__ int   g_ei_is64;
__device__ int   g_bt_is64;

__device__ __forceinline__ uint32_t smem_u32(const void* p) {
    uint32_t a;
    asm("{ .reg .u64 t; cvta.to.shared.u64 t, %1; cvt.u32.u64 %0, t; }"
        : "=r"(a) : "l"(p));
    return a;
}

__device__ __forceinline__ void ldsm_x4(uint32_t* r, uint32_t addr) {
    asm volatile("ldmatrix.sync.aligned.m8n8.x4.shared.b16 {%0,%1,%2,%3}, [%4];"
                 : "=r"(r[0]), "=r"(r[1]), "=r"(r[2]), "=r"(r[3]) : "r"(addr));
}

__device__ __forceinline__ void mma_bf16(float* d, const uint32_t* a,
                                         uint32_t b0, uint32_t b1) {
    asm volatile("mma.sync.aligned.m16n8k16.row.col.f32.bf16.bf16.f32 "
                 "{%0,%1,%2,%3}, {%4,%5,%6,%7}, {%8,%9}, {%0,%1,%2,%3};"
                 : "+f"(d[0]), "+f"(d[1]), "+f"(d[2]), "+f"(d[3])
                 : "r"(a[0]), "r"(a[1]), "r"(a[2]), "r"(a[3]),
                   "r"(b0), "r"(b1));
}

__device__ __forceinline__ void mma_fp16(float* d, const uint32_t* a,
                                         uint32_t b0, uint32_t b1) {
    asm volatile("mma.sync.aligned.m16n8k16.row.col.f32.f16.f16.f32 "
                 "{%0,%1,%2,%3}, {%4,%5,%6,%7}, {%8,%9}, {%0,%1,%2,%3};"
                 : "+f"(d[0]), "+f"(d[1]), "+f"(d[2]), "+f"(d[3])
                 : "r"(a[0]), "r"(a[1]), "r"(a[2]), "r"(a[3]),
                   "r"(b0), "r"(b1));
}

__device__ __forceinline__ float softplus_f(float x) {
    return fmaxf(x, 0.0f) + log1pf(expf(-fabsf(x)));
}

// ===========================================================================
__global__ void detect_dtype_kernel(const int* __restrict__ ei,
                                    const int* __restrict__ bt) {
    if (threadIdx.x == 0 && blockIdx.x == 0) {
        int e64 = 1, b64 = 1;
        #pragma unroll 1
        for (int i = 0; i < 64; i++) if (ei[2 * i + 1] != 0) { e64 = 0; break; }
        #pragma unroll 1
        for (int i = 0; i < 64; i++) if (bt[2 * i + 1] != 0) { b64 = 0; break; }
        g_ei_is64 = e64;
        g_bt_is64 = b64;
    }
}

__global__ void cemb_kernel(const float* __restrict__ embed,
                            const float* __restrict__ W1,
                            const float* __restrict__ b1) {
    int idx = blockIdx.x * 256 + threadIdx.x;
    if (idx < 13 * 128) {
        int t = idx >> 7, j = idx & 127;
        float s = b1[j];
        #pragma unroll
        for (int k = 0; k < 32; k++)
            s = fmaf(embed[t * 32 + k], W1[(256 + k) * 128 + j], s);
        g_C[idx] = s;
    }
}

// ===========================================================================
// Node GEMM on mma.sync (unchanged from R5/R10 pass — bf16 3-term, 1e-6 err)
// ===========================================================================
#define NROWB 272
#define NOFF_AHI 0
#define NOFF_ALO (64 * NROWB)
#define NOFF_WHI (2 * 64 * NROWB)
#define NOFF_WLO (2 * 64 * NROWB + 128 * NROWB)
#define NODE_SMEM (2 * 64 * NROWB + 2 * 128 * NROWB)

__global__ void __launch_bounds__(256, 2)
node_mma_kernel(const float* __restrict__ z,
                const float* __restrict__ W1,
                int nNodes, int nTilesN)
{
    extern __shared__ char sb[];
    const uint32_t base = smem_u32(sb);
    char* Ahi = sb + NOFF_AHI;
    char* Alo = sb + NOFF_ALO;
    char* Whi = sb + NOFF_WHI;
    char* Wlo = sb + NOFF_WLO;

    const int tid  = threadIdx.x;
    const int wid  = tid >> 5;
    const int lane = tid & 31;
    const int g    = lane >> 2;
    const int tg   = lane & 3;

    const int halfStride = gridDim.x >> 1;
    const int half = (blockIdx.x >= halfStride) ? 1 : 0;
    const int t0   = blockIdx.x - half * halfStride;
    const int krow = half * 128;

    for (int i = tid; i < 128 * 128; i += 256) {
        int k = i >> 7, n = i & 127;
        float w = W1[(krow + k) * 128 + n];
        __nv_bfloat16 hi = __float2bfloat16(w);
        float lof = w - __bfloat162float(hi);
        uint32_t off = (uint32_t)n * NROWB + (uint32_t)k * 2;
        *(__nv_bfloat16*)(Whi + off) = hi;
        *(__nv_bfloat16*)(Wlo + off) = __float2bfloat16(lof);
    }

    const uint32_t rowoff = (uint32_t)(((lane & 7) + ((lane & 8) ? 8 : 0)) * NROWB
                                       + ((lane & 16) ? 16 : 0));
    const int mt = wid & 3;
    const int ng = (wid >> 2) * 64;
    const uint32_t aHiB = base + NOFF_AHI + (uint32_t)(mt * 16) * NROWB + rowoff;
    const uint32_t aLoB = base + NOFF_ALO + (uint32_t)(mt * 16) * NROWB + rowoff;
    const uint32_t wHiB = base + NOFF_WHI + (uint32_t)ng * NROWB + rowoff;
    const uint32_t wLoB = base + NOFF_WLO + (uint32_t)ng * NROWB + rowoff;

    const float4* z4 = (const float4*)z;

    for (int t = t0; t < nTilesN; t += halfStride) {
        const int nb = t * 64;
        __syncthreads();

        #pragma unroll 2
        for (int idx = tid; idx < 64 * 32; idx += 256) {
            int e = idx >> 5, c = idx & 31;
            float4 v = make_float4(0.f, 0.f, 0.f, 0.f);
            if (nb + e < nNodes) v = z4[(size_t)(nb + e) * 32 + c];
            union { uint2 u; __nv_bfloat16 h[4]; } ph, pl;
            ph.h[0] = __float2bfloat16(v.x);
            ph.h[1] = __float2bfloat16(v.y);
            ph.h[2] = __float2bfloat16(v.z);
            ph.h[3] = __float2bfloat16(v.w);
            pl.h[0] = __float2bfloat16(v.x - __bfloat162float(ph.h[0]));
            pl.h[1] = __float2bfloat16(v.y - __bfloat162float(ph.h[1]));
            pl.h[2] = __float2bfloat16(v.z - __bfloat162float(ph.h[2]));
            pl.h[3] = __float2bfloat16(v.w - __bfloat162float(ph.h[3]));
            uint32_t off = (uint32_t)e * NROWB + (uint32_t)c * 8;
            *(uint2*)(Ahi + off) = ph.u;
            *(uint2*)(Alo + off) = pl.u;
        }
        __syncthreads();

        float D[8][4];
        #pragma unroll
        for (int i = 0; i < 8; i++)
            #pragma unroll
            for (int j = 0; j < 4; j++) D[i][j] = 0.f;

        #pragma unroll
        for (int ks = 0; ks < 8; ks++) {
            uint32_t ah[4], al[4];
            ldsm_x4(ah, aHiB + ks * 32);
            ldsm_x4(al, aLoB + ks * 32);
            #pragma unroll
            for (int p = 0; p < 4; p++) {
                uint32_t bh[4], bl[4];
                ldsm_x4(bh, wHiB + (uint32_t)(p * 16) * NROWB + ks * 32);
                ldsm_x4(bl, wLoB + (uint32_t)(p * 16) * NROWB + ks * 32);
                mma_bf16(D[2 * p],     ah, bh[0], bh[2]);
                mma_bf16(D[2 * p],     ah, bl[0], bl[2]);
                mma_bf16(D[2 * p],     al, bh[0], bh[2]);
                mma_bf16(D[2 * p + 1], ah, bh[1], bh[3]);
                mma_bf16(D[2 * p + 1], ah, bl[1], bl[3]);
                mma_bf16(D[2 * p + 1], al, bh[1], bh[3]);
            }
        }

        {
            int node0 = nb + mt * 16 + g;
            int cbase = half * 128 + ng + tg * 2;
            if (node0 < nNodes) {
                float* r = &g_PQ[(size_t)node0 * 256 + cbase];
                #pragma unroll
                for (int j = 0; j < 8; j++)
                    *(float2*)(r + j * 8) = make_float2(D[j][0], D[j][1]);
            }
            int node1 = node0 + 8;
            if (node1 < nNodes) {
                float* r = &g_PQ[(size_t)node1 * 256 + cbase];
                #pragma unroll
                for (int j = 0; j < 8; j++)
                    *(float2*)(r + j * 8) = make_float2(D[j][2], D[j][3]);
            }
        }
    }
}

// ===========================================================================
// Edge kernel: fp16 single-A / split-W, warp-autonomous, 3 CTAs/SM
// ===========================================================================
#define ETILE  128
#define ROWB   272
#define OFF_A    0
#define OFF_WHI  (OFF_A + 128 * ROWB)     // 34816
#define OFF_WLO  (OFF_WHI + 64 * ROWB)    // 52224
#define OFF_BW   (OFF_WLO + 64 * ROWB)    // 69632
#define EDGE_SMEM (OFF_BW + 64 * 8)       // 70144

__global__ void __launch_bounds__(256, 3)
edge_mma_kernel(const void*  __restrict__ eiv,
                const void*  __restrict__ btv,
                const float* __restrict__ W2,
                const float* __restrict__ b2,
                const float* __restrict__ W3,
                const float* __restrict__ b3,
                float* __restrict__ out,
                int E, int nTiles)
{
    extern __shared__ char sb[];
    const uint32_t base = smem_u32(sb);

    char*   Ah  = sb + OFF_A;
    char*   Whi = sb + OFF_WHI;
    char*   Wlo = sb + OFF_WLO;
    float2* sBW = (float2*)(sb + OFF_BW);

    const int tid  = threadIdx.x;
    const int wid  = tid >> 5;
    const int lane = tid & 31;
    const int g    = lane >> 2;
    const int tg   = lane & 3;
    const int ei64 = g_ei_is64, bt64 = g_bt_is64;

    // ---- one-time staging: W2 split fp16 hi/lo, b2/W3 ----
    if (tid < 64) sBW[tid] = make_float2(b2[tid], W3[tid]);
    for (int i = tid; i < 128 * 64; i += 256) {
        int k = i >> 6, n = i & 63;
        float w = W2[i];
        __half hi = __float2half_rn(w);
        float lof = w - __half2float(hi);
        uint32_t off = (uint32_t)n * ROWB + (uint32_t)k * 2;
        *(__half*)(Whi + off) = hi;
        *(__half*)(Wlo + off) = __float2half_rn(lof);
    }
    __syncthreads();

    const float b3v = __ldg(b3);

    const uint32_t rowoff = (uint32_t)(((lane & 7) + ((lane & 8) ? 8 : 0)) * ROWB
                                       + ((lane & 16) ? 16 : 0));
    const uint32_t aBase   = base + OFF_A + (uint32_t)(wid * 16) * ROWB + rowoff;
    const uint32_t wHiBase = base + OFF_WHI + rowoff;
    const uint32_t wLoBase = base + OFF_WLO + rowoff;

    const float4* PQ4 = (const float4*)g_PQ;
    const float4* gC4 = (const float4*)g_C;
    const int laneSel = lane & 15;

    for (int tile = blockIdx.x; tile < nTiles; tile += gridDim.x) {
        const int eW = tile * ETILE + wid * 16;   // this warp's 16 edges

        // ---- indices into registers: lanes 0..15 src, 16..31 dst ----
        int rs, rbt = 0;
        {
            int e = eW + laneSel;
            bool valid = e < E;
            size_t half = (lane < 16) ? 0 : (size_t)E;
            if (ei64) {
                const long long* p = (const long long*)eiv;
                rs = valid ? (int)p[half + e] : 0;
            } else {
                const int* p = (const int*)eiv;
                rs = valid ? p[half + e] : 0;
            }
            if (lane < 16) {
                rbt = valid ? (bt64 ? (int)((const long long*)btv)[e]
                                    : ((const int*)btv)[e]) : 0;
            }
        }
        __syncwarp();

        // ---- gather + relu -> fp16 A rows (single tile) ----
        #pragma unroll
        for (int i = 0; i < 16; i++) {
            int s = __shfl_sync(0xffffffffu, rs, i);
            int d = __shfl_sync(0xffffffffu, rs, 16 + i);
            int b = __shfl_sync(0xffffffffu, rbt, i);
            float4 p  = PQ4[(size_t)s * 64 + lane];
            float4 q  = PQ4[(size_t)d * 64 + 32 + lane];
            float4 cc = __ldg(&gC4[b * 32 + lane]);
            float g0 = fmaxf(p.x + q.x + cc.x, 0.f);
            float g1 = fmaxf(p.y + q.y + cc.y, 0.f);
            float g2 = fmaxf(p.z + q.z + cc.z, 0.f);
            float g3 = fmaxf(p.w + q.w + cc.w, 0.f);
            union { uint2 u; __half2 h[2]; } ph;
            ph.h[0] = __float22half2_rn(make_float2(g0, g1));
            ph.h[1] = __float22half2_rn(make_float2(g2, g3));
            uint32_t off = (uint32_t)(wid * 16 + i) * ROWB + (uint32_t)lane * 8;
            *(uint2*)(Ah + off) = ph.u;
        }
        __syncwarp();

        // ---- layer 2 MMAs: D = Ah (Wh + Wl), k=128 ----
        float D[8][4];
        #pragma unroll
        for (int i = 0; i < 8; i++)
            #pragma unroll
            for (int j = 0; j < 4; j++) D[i][j] = 0.f;

        #pragma unroll
        for (int ks = 0; ks < 8; ks++) {
            uint32_t ah[4];
            ldsm_x4(ah, aBase + ks * 32);
            #pragma unroll
            for (int p = 0; p < 4; p++) {
                uint32_t bh[4], bl[4];
                ldsm_x4(bh, wHiBase + (uint32_t)(p * 16) * ROWB + ks * 32);
                ldsm_x4(bl, wLoBase + (uint32_t)(p * 16) * ROWB + ks * 32);
                mma_fp16(D[2 * p],     ah, bh[0], bh[2]);
                mma_fp16(D[2 * p],     ah, bl[0], bl[2]);
                mma_fp16(D[2 * p + 1], ah, bh[1], bh[3]);
                mma_fp16(D[2 * p + 1], ah, bl[1], bl[3]);
            }
        }

        // ---- layer 3 + softplus ----
        {
            float p0 = 0.f, p1 = 0.f;
            #pragma unroll
            for (int nt = 0; nt < 8; nt++) {
                int n = nt * 8 + tg * 2;
                float2 bw0 = sBW[n];
                float2 bw1 = sBW[n + 1];
                p0 = fmaf(fmaxf(D[nt][0] + bw0.x, 0.f), bw0.y, p0);
                p0 = fmaf(fmaxf(D[nt][1] + bw1.x, 0.f), bw1.y, p0);
                p1 = fmaf(fmaxf(D[nt][2] + bw0.x, 0.f), bw0.y, p1);
                p1 = fmaf(fmaxf(D[nt][3] + bw1.x, 0.f), bw1.y, p1);
            }
            p0 += __shfl_xor_sync(0xffffffffu, p0, 1);
            p0 += __shfl_xor_sync(0xffffffffu, p0, 2);
            p1 += __shfl_xor_sync(0xffffffffu, p1, 1);
            p1 += __shfl_xor_sync(0xffffffffu, p1, 2);
            if (tg == 0) {
                int e0 = eW + g;
                if (e0 < E)     out[e0]     = softplus_f(p0 + b3v);
                if (e0 + 8 < E) out[e0 + 8] = softplus_f(p1 + b3v);
            }
        }
        // next iteration's __syncwarp orders A reuse; warp-private rows only
    }
}

// ===========================================================================
extern "C" void kernel_launch(void* const* d_in, const int* in_sizes, int n_in,
                              void* d_out, int out_size)
{
    const float* z     = (const float*)d_in[0];
    const void*  ei    = d_in[1];
    const void*  bt    = d_in[2];
    const float* embed = (const float*)d_in[3];
    const float* W1    = (const float*)d_in[4];
    const float* b1    = (const float*)d_in[5];
    const float* W2    = (const float*)d_in[6];
    const float* b2    = (const float*)d_in[7];
    const float* W3    = (const float*)d_in[8];
    const float* b3    = (const float*)d_in[9];
    float* out = (float*)d_out;

    int nNodes = in_sizes[0] / 128;
    int E = out_size;
    int nTiles  = (E + ETILE - 1) / ETILE;
    int nTilesN = (nNodes + 63) / 64;

    static int attr_done = 0;
    if (!attr_done) {
        cudaFuncSetAttribute(node_mma_kernel,
                             cudaFuncAttributeMaxDynamicSharedMemorySize, NODE_SMEM);
        cudaFuncSetAttribute(edge_mma_kernel,
                             cudaFuncAttributeMaxDynamicSharedMemorySize, EDGE_SMEM);
        attr_done = 1;
    }

    detect_dtype_kernel<<<1, 32>>>((const int*)ei, (const int*)bt);
    cemb_kernel<<<7, 256>>>(embed, W1, b1);

    node_mma_kernel<<<296, 256, NODE_SMEM>>>(z, W1, nNodes, nTilesN);

    int eg = nTiles < 444 ? nTiles : 444;
    edge_mma_kernel<<<eg, 256, EDGE_SMEM>>>(ei, bt, W2, b2, W3, b3, out, E, nTiles);
}

// round 14
// speedup vs baseline: 1.6702x; 1.1243x over previous
#include <cuda_runtime.h>
#include <cuda_bf16.h>
#include <cuda_fp16.h>
#include <math.h>
#include <stdint.h>

// ---------------------------------------------------------------------------
// BondLengthHead:
//   P = z @ W1[0:128,:], Q = z @ W1[128:256,:]   (node_mma_kernel, bf16 3-term,
//                                                 stored fp16)
//   C = embed @ W1[256:288,:] + b1               (13x128, stored fp16)
//   edge kernel (fp16, warp-autonomous, 3 CTAs/SM):
//     g = relu(fp32(P[src]) + fp32(Q[dst]) + fp32(C[bt])) -> fp16 A tile
//     W2 split fp16 hi/lo (W effectively exact)
//     D = Ah Wh + Ah Wl  (m16n8k16 HMMA fp16, f32 acc)
//     out = softplus(relu(D + b2) . W3 + b3)
// NOTE: harness compiles via compute_103 (no 'a') -> no tcgen05/TMEM allowed.
// ---------------------------------------------------------------------------

#define MAXN 100000

__device__ __half g_PQh[(size_t)MAXN * 256];   // [node][0:128]=P, [128:256]=Q
__device__ __half g_Ch[13 * 128];
__device__ int    g_ei_is64;
__device__ int    g_bt_is64;

__device__ __forceinline__ uint32_t smem_u32(const void* p) {
    uint32_t a;
    asm("{ .reg .u64 t; cvta.to.shared.u64 t, %1; cvt.u32.u64 %0, t; }"
        : "=r"(a) : "l"(p));
    return a;
}

__device__ __forceinline__ void ldsm_x4(uint32_t* r, uint32_t addr) {
    asm volatile("ldmatrix.sync.aligned.m8n8.x4.shared.b16 {%0,%1,%2,%3}, [%4];"
                 : "=r"(r[0]), "=r"(r[1]), "=r"(r[2]), "=r"(r[3]) : "r"(addr));
}

__device__ __forceinline__ void mma_bf16(float* d, const uint32_t* a,
                                         uint32_t b0, uint32_t b1) {
    asm volatile("mma.sync.aligned.m16n8k16.row.col.f32.bf16.bf16.f32 "
                 "{%0,%1,%2,%3}, {%4,%5,%6,%7}, {%8,%9}, {%0,%1,%2,%3};"
                 : "+f"(d[0]), "+f"(d[1]), "+f"(d[2]), "+f"(d[3])
                 : "r"(a[0]), "r"(a[1]), "r"(a[2]), "r"(a[3]),
                   "r"(b0), "r"(b1));
}

__device__ __forceinline__ void mma_fp16(float* d, const uint32_t* a,
                                         uint32_t b0, uint32_t b1) {
    asm volatile("mma.sync.aligned.m16n8k16.row.col.f32.f16.f16.f32 "
                 "{%0,%1,%2,%3}, {%4,%5,%6,%7}, {%8,%9}, {%0,%1,%2,%3};"
                 : "+f"(d[0]), "+f"(d[1]), "+f"(d[2]), "+f"(d[3])
                 : "r"(a[0]), "r"(a[1]), "r"(a[2]), "r"(a[3]),
                   "r"(b0), "r"(b1));
}

__device__ __forceinline__ float softplus_f(float x) {
    return fmaxf(x, 0.0f) + log1pf(expf(-fabsf(x)));
}

// ===========================================================================
__global__ void detect_dtype_kernel(const int* __restrict__ ei,
                                    const int* __restrict__ bt) {
    if (threadIdx.x == 0 && blockIdx.x == 0) {
        int e64 = 1, b64 = 1;
        #pragma unroll 1
        for (int i = 0; i < 64; i++) if (ei[2 * i + 1] != 0) { e64 = 0; break; }
        #pragma unroll 1
        for (int i = 0; i < 64; i++) if (bt[2 * i + 1] != 0) { b64 = 0; break; }
        g_ei_is64 = e64;
        g_bt_is64 = b64;
    }
}

__global__ void cemb_kernel(const float* __restrict__ embed,
                            const float* __restrict__ W1,
                            const float* __restrict__ b1) {
    int idx = blockIdx.x * 256 + threadIdx.x;
    if (idx < 13 * 128) {
        int t = idx >> 7, j = idx & 127;
        float s = b1[j];
        #pragma unroll
        for (int k = 0; k < 32; k++)
            s = fmaf(embed[t * 32 + k], W1[(256 + k) * 128 + j], s);
        g_Ch[idx] = __float2half_rn(s);
    }
}

// ===========================================================================
// Node GEMM on mma.sync (bf16 3-term), output stored fp16
// ===========================================================================
#define NROWB 272
#define NOFF_AHI 0
#define NOFF_ALO (64 * NROWB)
#define NOFF_WHI (2 * 64 * NROWB)
#define NOFF_WLO (2 * 64 * NROWB + 128 * NROWB)
#define NODE_SMEM (2 * 64 * NROWB + 2 * 128 * NROWB)

__global__ void __launch_bounds__(256, 2)
node_mma_kernel(const float* __restrict__ z,
                const float* __restrict__ W1,
                int nNodes, int nTilesN)
{
    extern __shared__ char sb[];
    const uint32_t base = smem_u32(sb);
    char* Ahi = sb + NOFF_AHI;
    char* Alo = sb + NOFF_ALO;
    char* Whi = sb + NOFF_WHI;
    char* Wlo = sb + NOFF_WLO;

    const int tid  = threadIdx.x;
    const int wid  = tid >> 5;
    const int lane = tid & 31;
    const int g    = lane >> 2;
    const int tg   = lane & 3;

    const int halfStride = gridDim.x >> 1;
    const int half = (blockIdx.x >= halfStride) ? 1 : 0;
    const int t0   = blockIdx.x - half * halfStride;
    const int krow = half * 128;

    for (int i = tid; i < 128 * 128; i += 256) {
        int k = i >> 7, n = i & 127;
        float w = W1[(krow + k) * 128 + n];
        __nv_bfloat16 hi = __float2bfloat16(w);
        float lof = w - __bfloat162float(hi);
        uint32_t off = (uint32_t)n * NROWB + (uint32_t)k * 2;
        *(__nv_bfloat16*)(Whi + off) = hi;
        *(__nv_bfloat16*)(Wlo + off) = __float2bfloat16(lof);
    }

    const uint32_t rowoff = (uint32_t)(((lane & 7) + ((lane & 8) ? 8 : 0)) * NROWB
                                       + ((lane & 16) ? 16 : 0));
    const int mt = wid & 3;
    const int ng = (wid >> 2) * 64;
    const uint32_t aHiB = base + NOFF_AHI + (uint32_t)(mt * 16) * NROWB + rowoff;
    const uint32_t aLoB = base + NOFF_ALO + (uint32_t)(mt * 16) * NROWB + rowoff;
    const uint32_t wHiB = base + NOFF_WHI + (uint32_t)ng * NROWB + rowoff;
    const uint32_t wLoB = base + NOFF_WLO + (uint32_t)ng * NROWB + rowoff;

    const float4* z4 = (const float4*)z;

    for (int t = t0; t < nTilesN; t += halfStride) {
        const int nb = t * 64;
        __syncthreads();

        #pragma unroll 2
        for (int idx = tid; idx < 64 * 32; idx += 256) {
            int e = idx >> 5, c = idx & 31;
            float4 v = make_float4(0.f, 0.f, 0.f, 0.f);
            if (nb + e < nNodes) v = z4[(size_t)(nb + e) * 32 + c];
            union { uint2 u; __nv_bfloat16 h[4]; } ph, pl;
            ph.h[0] = __float2bfloat16(v.x);
            ph.h[1] = __float2bfloat16(v.y);
            ph.h[2] = __float2bfloat16(v.z);
            ph.h[3] = __float2bfloat16(v.w);
            pl.h[0] = __float2bfloat16(v.x - __bfloat162float(ph.h[0]));
            pl.h[1] = __float2bfloat16(v.y - __bfloat162float(ph.h[1]));
            pl.h[2] = __float2bfloat16(v.z - __bfloat162float(ph.h[2]));
            pl.h[3] = __float2bfloat16(v.w - __bfloat162float(ph.h[3]));
            uint32_t off = (uint32_t)e * NROWB + (uint32_t)c * 8;
            *(uint2*)(Ahi + off) = ph.u;
            *(uint2*)(Alo + off) = pl.u;
        }
        __syncthreads();

        float D[8][4];
        #pragma unroll
        for (int i = 0; i < 8; i++)
            #pragma unroll
            for (int j = 0; j < 4; j++) D[i][j] = 0.f;

        #pragma unroll
        for (int ks = 0; ks < 8; ks++) {
            uint32_t ah[4], al[4];
            ldsm_x4(ah, aHiB + ks * 32);
            ldsm_x4(al, aLoB + ks * 32);
            #pragma unroll
            for (int p = 0; p < 4; p++) {
                uint32_t bh[4], bl[4];
                ldsm_x4(bh, wHiB + (uint32_t)(p * 16) * NROWB + ks * 32);
                ldsm_x4(bl, wLoB + (uint32_t)(p * 16) * NROWB + ks * 32);
                mma_bf16(D[2 * p],     ah, bh[0], bh[2]);
                mma_bf16(D[2 * p],     ah, bl[0], bl[2]);
                mma_bf16(D[2 * p],     al, bh[0], bh[2]);
                mma_bf16(D[2 * p + 1], ah, bh[1], bh[3]);
                mma_bf16(D[2 * p + 1], ah, bl[1], bl[3]);
                mma_bf16(D[2 * p + 1], al, bh[1], bh[3]);
            }
        }

        // ---- store D -> g_PQh (fp16) ----
        {
            int node0 = nb + mt * 16 + g;
            int cbase = half * 128 + ng + tg * 2;
            if (node0 < nNodes) {
                __half* r = &g_PQh[(size_t)node0 * 256 + cbase];
                #pragma unroll
                for (int j = 0; j < 8; j++)
                    *(__half2*)(r + j * 8) =
                        __float22half2_rn(make_float2(D[j][0], D[j][1]));
            }
            int node1 = node0 + 8;
            if (node1 < nNodes) {
                __half* r = &g_PQh[(size_t)node1 * 256 + cbase];
                #pragma unroll
                for (int j = 0; j < 8; j++)
                    *(__half2*)(r + j * 8) =
                        __float22half2_rn(make_float2(D[j][2], D[j][3]));
            }
        }
    }
}

// ===========================================================================
// Edge kernel: fp16 PQ/C gather, fp16 single-A / split-W, warp-autonomous
// ===========================================================================
#define ETILE  128
#define ROWB   272
#define OFF_A    0
#define OFF_WHI  (OFF_A + 128 * ROWB)     // 34816
#define OFF_WLO  (OFF_WHI + 64 * ROWB)    // 52224
#define OFF_BW   (OFF_WLO + 64 * ROWB)    // 69632
#define EDGE_SMEM (OFF_BW + 64 * 8)       // 70144

__global__ void __launch_bounds__(256, 3)
edge_mma_kernel(const void*  __restrict__ eiv,
                const void*  __restrict__ btv,
                const float* __restrict__ W2,
                const float* __restrict__ b2,
                const float* __restrict__ W3,
                const float* __restrict__ b3,
                float* __restrict__ out,
                int E, int nTiles)
{
    extern __shared__ char sb[];
    const uint32_t base = smem_u32(sb);

    char*   Ah  = sb + OFF_A;
    char*   Whi = sb + OFF_WHI;
    char*   Wlo = sb + OFF_WLO;
    float2* sBW = (float2*)(sb + OFF_BW);

    const int tid  = threadIdx.x;
    const int wid  = tid >> 5;
    const int lane = tid & 31;
    const int g    = lane >> 2;
    const int tg   = lane & 3;
    const int ei64 = g_ei_is64, bt64 = g_bt_is64;

    // ---- one-time staging: W2 split fp16 hi/lo, b2/W3 ----
    if (tid < 64) sBW[tid] = make_float2(b2[tid], W3[tid]);
    for (int i = tid; i < 128 * 64; i += 256) {
        int k = i >> 6, n = i & 63;
        float w = W2[i];
        __half hi = __float2half_rn(w);
        float lof = w - __half2float(hi);
        uint32_t off = (uint32_t)n * ROWB + (uint32_t)k * 2;
        *(__half*)(Whi + off) = hi;
        *(__half*)(Wlo + off) = __float2half_rn(lof);
    }
    __syncthreads();

    const float b3v = __ldg(b3);

    const uint32_t rowoff = (uint32_t)(((lane & 7) + ((lane & 8) ? 8 : 0)) * ROWB
                                       + ((lane & 16) ? 16 : 0));
    const uint32_t aBase   = base + OFF_A + (uint32_t)(wid * 16) * ROWB + rowoff;
    const uint32_t wHiBase = base + OFF_WHI + rowoff;
    const uint32_t wLoBase = base + OFF_WLO + rowoff;

    // fp16 tables as uint2 (4 halves): node row = 64 uint2 (P 0..31, Q 32..63)
    const uint2* PQ2 = (const uint2*)g_PQh;
    const uint2* C2  = (const uint2*)g_Ch;    // 13 rows x 32 uint2
    const int laneSel = lane & 15;

    for (int tile = blockIdx.x; tile < nTiles; tile += gridDim.x) {
        const int eW = tile * ETILE + wid * 16;   // this warp's 16 edges

        // ---- indices into registers: lanes 0..15 src, 16..31 dst ----
        int rs, rbt = 0;
        {
            int e = eW + laneSel;
            bool valid = e < E;
            size_t half = (lane < 16) ? 0 : (size_t)E;
            if (ei64) {
                const long long* p = (const long long*)eiv;
                rs = valid ? (int)p[half + e] : 0;
            } else {
                const int* p = (const int*)eiv;
                rs = valid ? p[half + e] : 0;
            }
            if (lane < 16) {
                rbt = valid ? (bt64 ? (int)((const long long*)btv)[e]
                                    : ((const int*)btv)[e]) : 0;
            }
        }
        __syncwarp();

        // ---- gather (fp16) + fp32 add + relu -> fp16 A rows ----
        #pragma unroll
        for (int i = 0; i < 16; i++) {
            int s = __shfl_sync(0xffffffffu, rs, i);
            int d = __shfl_sync(0xffffffffu, rs, 16 + i);
            int b = __shfl_sync(0xffffffffu, rbt, i);
            uint2 pu = PQ2[(size_t)s * 64 + lane];
            uint2 qu = PQ2[(size_t)d * 64 + 32 + lane];
            uint2 cu = __ldg(&C2[b * 32 + lane]);
            float2 p0 = __half22float2(*(__half2*)&pu.x);
            float2 p1 = __half22float2(*(__half2*)&pu.y);
            float2 q0 = __half22float2(*(__half2*)&qu.x);
            float2 q1 = __half22float2(*(__half2*)&qu.y);
            float2 c0 = __half22float2(*(__half2*)&cu.x);
            float2 c1 = __half22float2(*(__half2*)&cu.y);
            float g0 = fmaxf(p0.x + q0.x + c0.x, 0.f);
            float g1 = fmaxf(p0.y + q0.y + c0.y, 0.f);
            float g2 = fmaxf(p1.x + q1.x + c1.x, 0.f);
            float g3 = fmaxf(p1.y + q1.y + c1.y, 0.f);
            union { uint2 u; __half2 h[2]; } ph;
            ph.h[0] = __float22half2_rn(make_float2(g0, g1));
            ph.h[1] = __float22half2_rn(make_float2(g2, g3));
            uint32_t off = (uint32_t)(wid * 16 + i) * ROWB + (uint32_t)lane * 8;
            *(uint2*)(Ah + off) = ph.u;
        }
        __syncwarp();

        // ---- layer 2 MMAs: D = Ah (Wh + Wl), k=128 ----
        float D[8][4];
        #pragma unroll
        for (int i = 0; i < 8; i++)
            #pragma unroll
            for (int j = 0; j < 4; j++) D[i][j] = 0.f;

        #pragma unroll
        for (int ks = 0; ks < 8; ks++) {
            uint32_t ah[4];
            ldsm_x4(ah, aBase + ks * 32);
            #pragma unroll
            for (int p = 0; p < 4; p++) {
                uint32_t bh[4], bl[4];
                ldsm_x4(bh, wHiBase + (uint32_t)(p * 16) * ROWB + ks * 32);
                ldsm_x4(bl, wLoBase + (uint32_t)(p * 16) * ROWB + ks * 32);
                mma_fp16(D[2 * p],     ah, bh[0], bh[2]);
                mma_fp16(D[2 * p],     ah, bl[0], bl[2]);
                mma_fp16(D[2 * p + 1], ah, bh[1], bh[3]);
                mma_fp16(D[2 * p + 1], ah, bl[1], bl[3]);
            }
        }

        // ---- layer 3 + softplus ----
        {
            float p0 = 0.f, p1 = 0.f;
            #pragma unroll
            for (int nt = 0; nt < 8; nt++) {
                int n = nt * 8 + tg * 2;
                float2 bw0 = sBW[n];
                float2 bw1 = sBW[n + 1];
                p0 = fmaf(fmaxf(D[nt][0] + bw0.x, 0.f), bw0.y, p0);
                p0 = fmaf(fmaxf(D[nt][1] + bw1.x, 0.f), bw1.y, p0);
                p1 = fmaf(fmaxf(D[nt][2] + bw0.x, 0.f), bw0.y, p1);
                p1 = fmaf(fmaxf(D[nt][3] + bw1.x, 0.f), bw1.y, p1);
            }
            p0 += __shfl_xor_sync(0xffffffffu, p0, 1);
            p0 += __shfl_xor_sync(0xffffffffu, p0, 2);
            p1 += __shfl_xor_sync(0xffffffffu, p1, 1);
            p1 += __shfl_xor_sync(0xffffffffu, p1, 2);
            if (tg == 0) {
                int e0 = eW + g;
                if (e0 < E)     out[e0]     = softplus_f(p0 + b3v);
                if (e0 + 8 < E) out[e0 + 8] = softplus_f(p1 + b3v);
            }
        }
        // next iteration's __syncwarp orders A reuse; warp-private rows only
    }
}

// ===========================================================================
extern "C" void kernel_launch(void* const* d_in, const int* in_sizes, int n_in,
                              void* d_out, int out_size)
{
    const float* z     = (const float*)d_in[0];
    const void*  ei    = d_in[1];
    const void*  bt    = d_in[2];
    const float* embed = (const float*)d_in[3];
    const float* W1    = (const float*)d_in[4];
    const float* b1    = (const float*)d_in[5];
    const float* W2    = (const float*)d_in[6];
    const float* b2    = (const float*)d_in[7];
    const float* W3    = (const float*)d_in[8];
    const float* b3    = (const float*)d_in[9];
    float* out = (float*)d_out;

    int nNodes = in_sizes[0] / 128;
    int E = out_size;
    int nTiles  = (E + ETILE - 1) / ETILE;
    int nTilesN = (nNodes + 63) / 64;

    static int attr_done = 0;
    if (!attr_done) {
        cudaFuncSetAttribute(node_mma_kernel,
                             cudaFuncAttributeMaxDynamicSharedMemorySize, NODE_SMEM);
        cudaFuncSetAttribute(edge_mma_kernel,
                             cudaFuncAttributeMaxDynamicSharedMemorySize, EDGE_SMEM);
        attr_done = 1;
    }

    detect_dtype_kernel<<<1, 32>>>((const int*)ei, (const int*)bt);
    cemb_kernel<<<7, 256>>>(embed, W1, b1);

    node_mma_kernel<<<296, 256, NODE_SMEM>>>(z, W1, nNodes, nTilesN);

    int eg = nTiles < 444 ? nTiles : 444;
    edge_mma_kernel<<<eg, 256, EDGE_SMEM>>>(ei, bt, W2, b2, W3, b3, out, E, nTiles);
}

// round 15
// speedup vs baseline: 2.0554x; 1.2306x over previous
#include <cuda_runtime.h>
#include <cuda_bf16.h>
#include <cuda_fp16.h>
#include <math.h>
#include <stdint.h>

// ---------------------------------------------------------------------------
// BondLengthHead (all-fp16 tensor path):
//   P = z @ W1[0:128,:], Q = z @ W1[128:256,:]
//     node_mma_kernel: A = fp16(z) single tile, W1 split fp16 hi/lo (2-term)
//     P/Q stored fp16
//   C = embed @ W1[256:288,:] + b1  (13x128, stored fp16)
//   edge kernel (warp-autonomous, 3 CTAs/SM):
//     g = relu(fp32(P[src]) + fp32(Q[dst]) + fp32(C[bt])) -> fp16 A tile
//     D = Ah * fp16(W2)   (m16n8k16 HMMA, f32 acc, single term)
//     out = softplus(relu(D + b2) . W3 + b3)
// NOTE: harness compiles via compute_103 (no 'a') -> no tcgen05/TMEM allowed.
// ---------------------------------------------------------------------------

#define MAXN 100000

__device__ __half g_PQh[(size_t)MAXN * 256];   // [node][0:128]=P, [128:256]=Q
__device__ __half g_Ch[13 * 128];
__device__ int    g_ei_is64;
__device__ int    g_bt_is64;

__device__ __forceinline__ uint32_t smem_u32(const void* p) {
    uint32_t a;
    asm("{ .reg .u64 t; cvta.to.shared.u64 t, %1; cvt.u32.u64 %0, t; }"
        : "=r"(a) : "l"(p));
    return a;
}

__device__ __forceinline__ void ldsm_x4(uint32_t* r, uint32_t addr) {
    asm volatile("ldmatrix.sync.aligned.m8n8.x4.shared.b16 {%0,%1,%2,%3}, [%4];"
                 : "=r"(r[0]), "=r"(r[1]), "=r"(r[2]), "=r"(r[3]) : "r"(addr));
}

__device__ __forceinline__ void mma_fp16(float* d, const uint32_t* a,
                                         uint32_t b0, uint32_t b1) {
    asm volatile("mma.sync.aligned.m16n8k16.row.col.f32.f16.f16.f32 "
                 "{%0,%1,%2,%3}, {%4,%5,%6,%7}, {%8,%9}, {%0,%1,%2,%3};"
                 : "+f"(d[0]), "+f"(d[1]), "+f"(d[2]), "+f"(d[3])
                 : "r"(a[0]), "r"(a[1]), "r"(a[2]), "r"(a[3]),
                   "r"(b0), "r"(b1));
}

__device__ __forceinline__ float softplus_f(float x) {
    return fmaxf(x, 0.0f) + log1pf(expf(-fabsf(x)));
}

// ===========================================================================
__global__ void detect_dtype_kernel(const int* __restrict__ ei,
                                    const int* __restrict__ bt) {
    if (threadIdx.x == 0 && blockIdx.x == 0) {
        int e64 = 1, b64 = 1;
        #pragma unroll 1
        for (int i = 0; i < 64; i++) if (ei[2 * i + 1] != 0) { e64 = 0; break; }
        #pragma unroll 1
        for (int i = 0; i < 64; i++) if (bt[2 * i + 1] != 0) { b64 = 0; break; }
        g_ei_is64 = e64;
        g_bt_is64 = b64;
    }
}

__global__ void cemb_kernel(const float* __restrict__ embed,
                            const float* __restrict__ W1,
                            const float* __restrict__ b1) {
    int idx = blockIdx.x * 256 + threadIdx.x;
    if (idx < 13 * 128) {
        int t = idx >> 7, j = idx & 127;
        float s = b1[j];
        #pragma unroll
        for (int k = 0; k < 32; k++)
            s = fmaf(embed[t * 32 + k], W1[(256 + k) * 128 + j], s);
        g_Ch[idx] = __float2half_rn(s);
    }
}

// ===========================================================================
// Node GEMM: A = fp16(z) single, W1 split fp16 hi/lo (2-term), out fp16
// ===========================================================================
#define NROWB 272
#define NOFF_A   0
#define NOFF_WHI (64 * NROWB)                    // 17408
#define NOFF_WLO (NOFF_WHI + 128 * NROWB)        // 52224
#define NODE_SMEM (NOFF_WLO + 128 * NROWB)       // 87040

__global__ void __launch_bounds__(256, 2)
node_mma_kernel(const float* __restrict__ z,
                const float* __restrict__ W1,
                int nNodes, int nTilesN)
{
    extern __shared__ char sb[];
    const uint32_t base = smem_u32(sb);
    char* Ah  = sb + NOFF_A;
    char* Whi = sb + NOFF_WHI;
    char* Wlo = sb + NOFF_WLO;

    const int tid  = threadIdx.x;
    const int wid  = tid >> 5;
    const int lane = tid & 31;
    const int g    = lane >> 2;
    const int tg   = lane & 3;

    const int halfStride = gridDim.x >> 1;
    const int half = (blockIdx.x >= halfStride) ? 1 : 0;
    const int t0   = blockIdx.x - half * halfStride;
    const int krow = half * 128;

    // ---- stage W1T half (128 n x 128 k), split fp16 hi/lo (once) ----
    for (int i = tid; i < 128 * 128; i += 256) {
        int k = i >> 7, n = i & 127;
        float w = W1[(krow + k) * 128 + n];
        __half hi = __float2half_rn(w);
        float lof = w - __half2float(hi);
        uint32_t off = (uint32_t)n * NROWB + (uint32_t)k * 2;
        *(__half*)(Whi + off) = hi;
        *(__half*)(Wlo + off) = __float2half_rn(lof);
    }

    const uint32_t rowoff = (uint32_t)(((lane & 7) + ((lane & 8) ? 8 : 0)) * NROWB
                                       + ((lane & 16) ? 16 : 0));
    const int mt = wid & 3;
    const int ng = (wid >> 2) * 64;
    const uint32_t aB   = base + NOFF_A + (uint32_t)(mt * 16) * NROWB + rowoff;
    const uint32_t wHiB = base + NOFF_WHI + (uint32_t)ng * NROWB + rowoff;
    const uint32_t wLoB = base + NOFF_WLO + (uint32_t)ng * NROWB + rowoff;

    const float4* z4 = (const float4*)z;

    for (int t = t0; t < nTilesN; t += halfStride) {
        const int nb = t * 64;
        __syncthreads();

        // ---- stage A: 64 nodes x 128 k, fp16 single ----
        #pragma unroll 2
        for (int idx = tid; idx < 64 * 32; idx += 256) {
            int e = idx >> 5, c = idx & 31;
            float4 v = make_float4(0.f, 0.f, 0.f, 0.f);
            if (nb + e < nNodes) v = z4[(size_t)(nb + e) * 32 + c];
            union { uint2 u; __half2 h[2]; } ph;
            ph.h[0] = __float22half2_rn(make_float2(v.x, v.y));
            ph.h[1] = __float22half2_rn(make_float2(v.z, v.w));
            uint32_t off = (uint32_t)e * NROWB + (uint32_t)c * 8;
            *(uint2*)(Ah + off) = ph.u;
        }
        __syncthreads();

        float D[8][4];
        #pragma unroll
        for (int i = 0; i < 8; i++)
            #pragma unroll
            for (int j = 0; j < 4; j++) D[i][j] = 0.f;

        #pragma unroll
        for (int ks = 0; ks < 8; ks++) {
            uint32_t ah[4];
            ldsm_x4(ah, aB + ks * 32);
            #pragma unroll
            for (int p = 0; p < 4; p++) {
                uint32_t bh[4], bl[4];
                ldsm_x4(bh, wHiB + (uint32_t)(p * 16) * NROWB + ks * 32);
                ldsm_x4(bl, wLoB + (uint32_t)(p * 16) * NROWB + ks * 32);
                mma_fp16(D[2 * p],     ah, bh[0], bh[2]);
                mma_fp16(D[2 * p],     ah, bl[0], bl[2]);
                mma_fp16(D[2 * p + 1], ah, bh[1], bh[3]);
                mma_fp16(D[2 * p + 1], ah, bl[1], bl[3]);
            }
        }

        // ---- store D -> g_PQh (fp16) ----
        {
            int node0 = nb + mt * 16 + g;
            int cbase = half * 128 + ng + tg * 2;
            if (node0 < nNodes) {
                __half* r = &g_PQh[(size_t)node0 * 256 + cbase];
                #pragma unroll
                for (int j = 0; j < 8; j++)
                    *(__half2*)(r + j * 8) =
                        __float22half2_rn(make_float2(D[j][0], D[j][1]));
            }
            int node1 = node0 + 8;
            if (node1 < nNodes) {
                __half* r = &g_PQh[(size_t)node1 * 256 + cbase];
                #pragma unroll
                for (int j = 0; j < 8; j++)
                    *(__half2*)(r + j * 8) =
                        __float22half2_rn(make_float2(D[j][2], D[j][3]));
            }
        }
    }
}

// ===========================================================================
// Edge kernel: fp16 gather, single-term fp16 MMA, warp-autonomous, 3 CTAs/SM
// ===========================================================================
#define ETILE  128
#define ROWB   272
#define OFF_A    0
#define OFF_WHI  (OFF_A + 128 * ROWB)     // 34816
#define OFF_BW   (OFF_WHI + 64 * ROWB)    // 52224
#define EDGE_SMEM (OFF_BW + 64 * 8)       // 52736

__global__ void __launch_bounds__(256, 3)
edge_mma_kernel(const void*  __restrict__ eiv,
                const void*  __restrict__ btv,
                const float* __restrict__ W2,
                const float* __restrict__ b2,
                const float* __restrict__ W3,
                const float* __restrict__ b3,
                float* __restrict__ out,
                int E, int nTiles)
{
    extern __shared__ char sb[];
    const uint32_t base = smem_u32(sb);

    char*   Ah  = sb + OFF_A;
    char*   Whi = sb + OFF_WHI;
    float2* sBW = (float2*)(sb + OFF_BW);

    const int tid  = threadIdx.x;
    const int wid  = tid >> 5;
    const int lane = tid & 31;
    const int g    = lane >> 2;
    const int tg   = lane & 3;
    const int ei64 = g_ei_is64, bt64 = g_bt_is64;

    // ---- one-time staging: W2 fp16, b2/W3 ----
    if (tid < 64) sBW[tid] = make_float2(b2[tid], W3[tid]);
    for (int i = tid; i < 128 * 64; i += 256) {
        int k = i >> 6, n = i & 63;
        uint32_t off = (uint32_t)n * ROWB + (uint32_t)k * 2;
        *(__half*)(Whi + off) = __float2half_rn(W2[i]);
    }
    __syncthreads();

    const float b3v = __ldg(b3);

    const uint32_t rowoff = (uint32_t)(((lane & 7) + ((lane & 8) ? 8 : 0)) * ROWB
                                       + ((lane & 16) ? 16 : 0));
    const uint32_t aBase   = base + OFF_A + (uint32_t)(wid * 16) * ROWB + rowoff;
    const uint32_t wHiBase = base + OFF_WHI + rowoff;

    // fp16 tables as uint2 (4 halves): node row = 64 uint2 (P 0..31, Q 32..63)
    const uint2* PQ2 = (const uint2*)g_PQh;
    const uint2* C2  = (const uint2*)g_Ch;    // 13 rows x 32 uint2
    const int laneSel = lane & 15;

    for (int tile = blockIdx.x; tile < nTiles; tile += gridDim.x) {
        const int eW = tile * ETILE + wid * 16;   // this warp's 16 edges

        // ---- indices into registers: lanes 0..15 src, 16..31 dst ----
        int rs, rbt = 0;
        {
            int e = eW + laneSel;
            bool valid = e < E;
            size_t half = (lane < 16) ? 0 : (size_t)E;
            if (ei64) {
                const long long* p = (const long long*)eiv;
                rs = valid ? (int)p[half + e] : 0;
            } else {
                const int* p = (const int*)eiv;
                rs = valid ? p[half + e] : 0;
            }
            if (lane < 16) {
                rbt = valid ? (bt64 ? (int)((const long long*)btv)[e]
                                    : ((const int*)btv)[e]) : 0;
            }
        }
        __syncwarp();

        // ---- gather (fp16) + fp32 add + relu -> fp16 A rows ----
        #pragma unroll
        for (int i = 0; i < 16; i++) {
            int s = __shfl_sync(0xffffffffu, rs, i);
            int d = __shfl_sync(0xffffffffu, rs, 16 + i);
            int b = __shfl_sync(0xffffffffu, rbt, i);
            uint2 pu = PQ2[(size_t)s * 64 + lane];
            uint2 qu = PQ2[(size_t)d * 64 + 32 + lane];
            uint2 cu = __ldg(&C2[b * 32 + lane]);
            float2 p0 = __half22float2(*(__half2*)&pu.x);
            float2 p1 = __half22float2(*(__half2*)&pu.y);
            float2 q0 = __half22float2(*(__half2*)&qu.x);
            float2 q1 = __half22float2(*(__half2*)&qu.y);
            float2 c0 = __half22float2(*(__half2*)&cu.x);
            float2 c1 = __half22float2(*(__half2*)&cu.y);
            float g0 = fmaxf(p0.x + q0.x + c0.x, 0.f);
            float g1 = fmaxf(p0.y + q0.y + c0.y, 0.f);
            float g2 = fmaxf(p1.x + q1.x + c1.x, 0.f);
            float g3 = fmaxf(p1.y + q1.y + c1.y, 0.f);
            union { uint2 u; __half2 h[2]; } ph;
            ph.h[0] = __float22half2_rn(make_float2(g0, g1));
            ph.h[1] = __float22half2_rn(make_float2(g2, g3));
            uint32_t off = (uint32_t)(wid * 16 + i) * ROWB + (uint32_t)lane * 8;
            *(uint2*)(Ah + off) = ph.u;
        }
        __syncwarp();

        // ---- layer 2 MMAs: D = Ah * W (single term), k=128 ----
        float D[8][4];
        #pragma unroll
        for (int i = 0; i < 8; i++)
            #pragma unroll
            for (int j = 0; j < 4; j++) D[i][j] = 0.f;

        #pragma unroll
        for (int ks = 0; ks < 8; ks++) {
            uint32_t ah[4];
            ldsm_x4(ah, aBase + ks * 32);
            #pragma unroll
            for (int p = 0; p < 4; p++) {
                uint32_t bh[4];
                ldsm_x4(bh, wHiBase + (uint32_t)(p * 16) * ROWB + ks * 32);
                mma_fp16(D[2 * p],     ah, bh[0], bh[2]);
                mma_fp16(D[2 * p + 1], ah, bh[1], bh[3]);
            }
        }

        // ---- layer 3 + softplus ----
        {
            float p0 = 0.f, p1 = 0.f;
            #pragma unroll
            for (int nt = 0; nt < 8; nt++) {
                int n = nt * 8 + tg * 2;
                float2 bw0 = sBW[n];
                float2 bw1 = sBW[n + 1];
                p0 = fmaf(fmaxf(D[nt][0] + bw0.x, 0.f), bw0.y, p0);
                p0 = fmaf(fmaxf(D[nt][1] + bw1.x, 0.f), bw1.y, p0);
                p1 = fmaf(fmaxf(D[nt][2] + bw0.x, 0.f), bw0.y, p1);
                p1 = fmaf(fmaxf(D[nt][3] + bw1.x, 0.f), bw1.y, p1);
            }
            p0 += __shfl_xor_sync(0xffffffffu, p0, 1);
            p0 += __shfl_xor_sync(0xffffffffu, p0, 2);
            p1 += __shfl_xor_sync(0xffffffffu, p1, 1);
            p1 += __shfl_xor_sync(0xffffffffu, p1, 2);
            if (tg == 0) {
                int e0 = eW + g;
                if (e0 < E)     out[e0]     = softplus_f(p0 + b3v);
                if (e0 + 8 < E) out[e0 + 8] = softplus_f(p1 + b3v);
            }
        }
        // next iteration's __syncwarp orders A reuse; warp-private rows only
    }
}

// ===========================================================================
extern "C" void kernel_launch(void* const* d_in, const int* in_sizes, int n_in,
                              void* d_out, int out_size)
{
    const float* z     = (const float*)d_in[0];
    const void*  ei    = d_in[1];
    const void*  bt    = d_in[2];
    const float* embed = (const float*)d_in[3];
    const float* W1    = (const float*)d_in[4];
    const float* b1    = (const float*)d_in[5];
    const float* W2    = (const float*)d_in[6];
    const float* b2    = (const float*)d_in[7];
    const float* W3    = (const float*)d_in[8];
    const float* b3    = (const float*)d_in[9];
    float* out = (float*)d_out;

    int nNodes = in_sizes[0] / 128;
    int E = out_size;
    int nTiles  = (E + ETILE - 1) / ETILE;
    int nTilesN = (nNodes + 63) / 64;

    static int attr_done = 0;
    if (!attr_done) {
        cudaFuncSetAttribute(node_mma_kernel,
                             cudaFuncAttributeMaxDynamicSharedMemorySize, NODE_SMEM);
        cudaFuncSetAttribute(edge_mma_kernel,
                             cudaFuncAttributeMaxDynamicSharedMemorySize, EDGE_SMEM);
        attr_done = 1;
    }

    detect_dtype_kernel<<<1, 32>>>((const int*)ei, (const int*)bt);
    cemb_kernel<<<7, 256>>>(embed, W1, b1);

    node_mma_kernel<<<296, 256, NODE_SMEM>>>(z, W1, nNodes, nTilesN);

    int eg = nTiles < 444 ? nTiles : 444;
    edge_mma_kernel<<<eg, 256, EDGE_SMEM>>>(ei, bt, W2, b2, W3, b3, out, E, nTiles);
}

// round 16
// speedup vs baseline: 2.4089x; 1.1720x over previous
#include <cuda_runtime.h>
#include <cuda_bf16.h>
#include <cuda_fp16.h>
#include <math.h>
#include <stdint.h>

// ---------------------------------------------------------------------------
// BondLengthHead (all-fp16 tensor path):
//   P = z @ W1[0:128,:], Q = z @ W1[128:256,:]
//     node_mma_kernel: A = fp16(z), W = fp16(W1) single-term, 3 CTAs/SM
//     P/Q stored fp16
//   C = embed @ W1[256:288,:] + b1  (13x128, stored fp16)
//   edge kernel (warp-autonomous, 3 CTAs/SM):
//     g = hmax2(P[src] + Q[dst] + C[bt], 0)   (half2-native)
//     D = A * fp16(W2)   (m16n8k16 HMMA, f32 acc)
//     out = softplus(relu(D + b2) . W3 + b3)
// NOTE: harness compiles via compute_103 (no 'a') -> no tcgen05/TMEM allowed.
// ---------------------------------------------------------------------------

#define MAXN 100000

__device__ __half g_PQh[(size_t)MAXN * 256];   // [node][0:128]=P, [128:256]=Q
__device__ __half g_Ch[13 * 128];
__device__ int    g_ei_is64;
__device__ int    g_bt_is64;

__device__ __forceinline__ uint32_t smem_u32(const void* p) {
    uint32_t a;
    asm("{ .reg .u64 t; cvta.to.shared.u64 t, %1; cvt.u32.u64 %0, t; }"
        : "=r"(a) : "l"(p));
    return a;
}

__device__ __forceinline__ void ldsm_x4(uint32_t* r, uint32_t addr) {
    asm volatile("ldmatrix.sync.aligned.m8n8.x4.shared.b16 {%0,%1,%2,%3}, [%4];"
                 : "=r"(r[0]), "=r"(r[1]), "=r"(r[2]), "=r"(r[3]) : "r"(addr));
}

__device__ __forceinline__ void mma_fp16(float* d, const uint32_t* a,
                                         uint32_t b0, uint32_t b1) {
    asm volatile("mma.sync.aligned.m16n8k16.row.col.f32.f16.f16.f32 "
                 "{%0,%1,%2,%3}, {%4,%5,%6,%7}, {%8,%9}, {%0,%1,%2,%3};"
                 : "+f"(d[0]), "+f"(d[1]), "+f"(d[2]), "+f"(d[3])
                 : "r"(a[0]), "r"(a[1]), "r"(a[2]), "r"(a[3]),
                   "r"(b0), "r"(b1));
}

__device__ __forceinline__ float softplus_f(float x) {
    return fmaxf(x, 0.0f) + log1pf(expf(-fabsf(x)));
}

// ===========================================================================
__global__ void detect_dtype_kernel(const int* __restrict__ ei,
                                    const int* __restrict__ bt) {
    if (threadIdx.x == 0 && blockIdx.x == 0) {
        int e64 = 1, b64 = 1;
        #pragma unroll 1
        for (int i = 0; i < 64; i++) if (ei[2 * i + 1] != 0) { e64 = 0; break; }
        #pragma unroll 1
        for (int i = 0; i < 64; i++) if (bt[2 * i + 1] != 0) { b64 = 0; break; }
        g_ei_is64 = e64;
        g_bt_is64 = b64;
    }
}

__global__ void cemb_kernel(const float* __restrict__ embed,
                            const float* __restrict__ W1,
                            const float* __restrict__ b1) {
    int idx = blockIdx.x * 256 + threadIdx.x;
    if (idx < 13 * 128) {
        int t = idx >> 7, j = idx & 127;
        float s = b1[j];
        #pragma unroll
        for (int k = 0; k < 32; k++)
            s = fmaf(embed[t * 32 + k], W1[(256 + k) * 128 + j], s);
        g_Ch[idx] = __float2half_rn(s);
    }
}

// ===========================================================================
// Node GEMM: A = fp16(z), W = fp16(W1) single-term, out fp16, 3 CTAs/SM
// ===========================================================================
#define NROWB 272
#define NOFF_A   0
#define NOFF_WHI (64 * NROWB)                    // 17408
#define NODE_SMEM (NOFF_WHI + 128 * NROWB)       // 52224

__global__ void __launch_bounds__(256, 3)
node_mma_kernel(const float* __restrict__ z,
                const float* __restrict__ W1,
                int nNodes, int nTilesN)
{
    extern __shared__ char sb[];
    const uint32_t base = smem_u32(sb);
    char* Ah  = sb + NOFF_A;
    char* Whi = sb + NOFF_WHI;

    const int tid  = threadIdx.x;
    const int wid  = tid >> 5;
    const int lane = tid & 31;
    const int g    = lane >> 2;
    const int tg   = lane & 3;

    const int halfStride = gridDim.x >> 1;
    const int half = (blockIdx.x >= halfStride) ? 1 : 0;
    const int t0   = blockIdx.x - half * halfStride;
    const int krow = half * 128;

    // ---- stage W1T half (128 n x 128 k), fp16 (once) ----
    for (int i = tid; i < 128 * 128; i += 256) {
        int k = i >> 7, n = i & 127;
        uint32_t off = (uint32_t)n * NROWB + (uint32_t)k * 2;
        *(__half*)(Whi + off) = __float2half_rn(W1[(krow + k) * 128 + n]);
    }

    const uint32_t rowoff = (uint32_t)(((lane & 7) + ((lane & 8) ? 8 : 0)) * NROWB
                                       + ((lane & 16) ? 16 : 0));
    const int mt = wid & 3;
    const int ng = (wid >> 2) * 64;
    const uint32_t aB   = base + NOFF_A + (uint32_t)(mt * 16) * NROWB + rowoff;
    const uint32_t wHiB = base + NOFF_WHI + (uint32_t)ng * NROWB + rowoff;

    const float4* z4 = (const float4*)z;

    for (int t = t0; t < nTilesN; t += halfStride) {
        const int nb = t * 64;
        __syncthreads();

        // ---- stage A: 64 nodes x 128 k, fp16 ----
        #pragma unroll 2
        for (int idx = tid; idx < 64 * 32; idx += 256) {
            int e = idx >> 5, c = idx & 31;
            float4 v = make_float4(0.f, 0.f, 0.f, 0.f);
            if (nb + e < nNodes) v = z4[(size_t)(nb + e) * 32 + c];
            union { uint2 u; __half2 h[2]; } ph;
            ph.h[0] = __float22half2_rn(make_float2(v.x, v.y));
            ph.h[1] = __float22half2_rn(make_float2(v.z, v.w));
            uint32_t off = (uint32_t)e * NROWB + (uint32_t)c * 8;
            *(uint2*)(Ah + off) = ph.u;
        }
        __syncthreads();

        float D[8][4];
        #pragma unroll
        for (int i = 0; i < 8; i++)
            #pragma unroll
            for (int j = 0; j < 4; j++) D[i][j] = 0.f;

        #pragma unroll
        for (int ks = 0; ks < 8; ks++) {
            uint32_t ah[4];
            ldsm_x4(ah, aB + ks * 32);
            #pragma unroll
            for (int p = 0; p < 4; p++) {
                uint32_t bh[4];
                ldsm_x4(bh, wHiB + (uint32_t)(p * 16) * NROWB + ks * 32);
                mma_fp16(D[2 * p],     ah, bh[0], bh[2]);
                mma_fp16(D[2 * p + 1], ah, bh[1], bh[3]);
            }
        }

        // ---- store D -> g_PQh (fp16) ----
        {
            int node0 = nb + mt * 16 + g;
            int cbase = half * 128 + ng + tg * 2;
            if (node0 < nNodes) {
                __half* r = &g_PQh[(size_t)node0 * 256 + cbase];
                #pragma unroll
                for (int j = 0; j < 8; j++)
                    *(__half2*)(r + j * 8) =
                        __float22half2_rn(make_float2(D[j][0], D[j][1]));
            }
            int node1 = node0 + 8;
            if (node1 < nNodes) {
                __half* r = &g_PQh[(size_t)node1 * 256 + cbase];
                #pragma unroll
                for (int j = 0; j < 8; j++)
                    *(__half2*)(r + j * 8) =
                        __float22half2_rn(make_float2(D[j][2], D[j][3]));
            }
        }
    }
}

// ===========================================================================
// Edge kernel: half2-native gather, single-term fp16 MMA, 3 CTAs/SM
// ===========================================================================
#define ETILE  128
#define ROWB   272
#define OFF_A    0
#define OFF_WHI  (OFF_A + 128 * ROWB)     // 34816
#define OFF_BW   (OFF_WHI + 64 * ROWB)    // 52224
#define EDGE_SMEM (OFF_BW + 32 * 16)      // 52736

__global__ void __launch_bounds__(256, 3)
edge_mma_kernel(const void*  __restrict__ eiv,
                const void*  __restrict__ btv,
                const float* __restrict__ W2,
                const float* __restrict__ b2,
                const float* __restrict__ W3,
                const float* __restrict__ b3,
                float* __restrict__ out,
                int E, int nTiles)
{
    extern __shared__ char sb[];
    const uint32_t base = smem_u32(sb);

    char*   Ah   = sb + OFF_A;
    char*   Whi  = sb + OFF_WHI;
    float4* sBW4 = (float4*)(sb + OFF_BW);   // [32]: (b2[2i],W3[2i],b2[2i+1],W3[2i+1])

    const int tid  = threadIdx.x;
    const int wid  = tid >> 5;
    const int lane = tid & 31;
    const int g    = lane >> 2;
    const int tg   = lane & 3;
    const int ei64 = g_ei_is64, bt64 = g_bt_is64;

    // ---- one-time staging: W2 fp16, packed b2/W3 ----
    if (tid < 32) {
        int n = tid * 2;
        sBW4[tid] = make_float4(b2[n], W3[n], b2[n + 1], W3[n + 1]);
    }
    for (int i = tid; i < 128 * 64; i += 256) {
        int k = i >> 6, n = i & 63;
        uint32_t off = (uint32_t)n * ROWB + (uint32_t)k * 2;
        *(__half*)(Whi + off) = __float2half_rn(W2[i]);
    }
    __syncthreads();

    const float b3v = __ldg(b3);

    const uint32_t rowoff = (uint32_t)(((lane & 7) + ((lane & 8) ? 8 : 0)) * ROWB
                                       + ((lane & 16) ? 16 : 0));
    const uint32_t aBase   = base + OFF_A + (uint32_t)(wid * 16) * ROWB + rowoff;
    const uint32_t wHiBase = base + OFF_WHI + rowoff;

    const uint2* PQ2 = (const uint2*)g_PQh;   // node row = 64 uint2 (P 0..31, Q 32..63)
    const uint2* C2  = (const uint2*)g_Ch;    // 13 rows x 32 uint2
    const int laneSel = lane & 15;

    for (int tile = blockIdx.x; tile < nTiles; tile += gridDim.x) {
        const int eW = tile * ETILE + wid * 16;   // this warp's 16 edges

        // ---- indices into registers: lanes 0..15 src, 16..31 dst ----
        int rs, rbt = 0;
        {
            int e = eW + laneSel;
            bool valid = e < E;
            size_t half = (lane < 16) ? 0 : (size_t)E;
            if (ei64) {
                const long long* p = (const long long*)eiv;
                rs = valid ? (int)p[half + e] : 0;
            } else {
                const int* p = (const int*)eiv;
                rs = valid ? p[half + e] : 0;
            }
            if (lane < 16) {
                rbt = valid ? (bt64 ? (int)((const long long*)btv)[e]
                                    : ((const int*)btv)[e]) : 0;
            }
        }
        __syncwarp();

        // ---- gather + half2 add + relu -> fp16 A rows ----
        const __half2 zero2 = __float2half2_rn(0.f);
        #pragma unroll
        for (int i = 0; i < 16; i++) {
            int s = __shfl_sync(0xffffffffu, rs, i);
            int d = __shfl_sync(0xffffffffu, rs, 16 + i);
            int b = __shfl_sync(0xffffffffu, rbt, i);
            uint2 pu = PQ2[(size_t)((uint32_t)s * 64u + lane)];
            uint2 qu = PQ2[(size_t)((uint32_t)d * 64u + 32u + lane)];
            uint2 cu = __ldg(&C2[b * 32 + lane]);
            union { uint2 u; __half2 h[2]; } ph;
            ph.h[0] = __hmax2(__hadd2(__hadd2(*(__half2*)&pu.x, *(__half2*)&qu.x),
                                      *(__half2*)&cu.x), zero2);
            ph.h[1] = __hmax2(__hadd2(__hadd2(*(__half2*)&pu.y, *(__half2*)&qu.y),
                                      *(__half2*)&cu.y), zero2);
            uint32_t off = (uint32_t)(wid * 16 + i) * ROWB + (uint32_t)lane * 8;
            *(uint2*)(Ah + off) = ph.u;
        }
        __syncwarp();

        // ---- layer 2 MMAs: D = A * W, k=128 ----
        float D[8][4];
        #pragma unroll
        for (int i = 0; i < 8; i++)
            #pragma unroll
            for (int j = 0; j < 4; j++) D[i][j] = 0.f;

        #pragma unroll
        for (int ks = 0; ks < 8; ks++) {
            uint32_t ah[4];
            ldsm_x4(ah, aBase + ks * 32);
            #pragma unroll
            for (int p = 0; p < 4; p++) {
                uint32_t bh[4];
                ldsm_x4(bh, wHiBase + (uint32_t)(p * 16) * ROWB + ks * 32);
                mma_fp16(D[2 * p],     ah, bh[0], bh[2]);
                mma_fp16(D[2 * p + 1], ah, bh[1], bh[3]);
            }
        }

        // ---- layer 3 + softplus (float4-packed b2/W3) ----
        {
            float p0 = 0.f, p1 = 0.f;
            #pragma unroll
            for (int nt = 0; nt < 8; nt++) {
                float4 bw = sBW4[nt * 4 + tg];   // n = nt*8 + tg*2, n+1
                p0 = fmaf(fmaxf(D[nt][0] + bw.x, 0.f), bw.y, p0);
                p0 = fmaf(fmaxf(D[nt][1] + bw.z, 0.f), bw.w, p0);
                p1 = fmaf(fmaxf(D[nt][2] + bw.x, 0.f), bw.y, p1);
                p1 = fmaf(fmaxf(D[nt][3] + bw.z, 0.f), bw.w, p1);
            }
            p0 += __shfl_xor_sync(0xffffffffu, p0, 1);
            p0 += __shfl_xor_sync(0xffffffffu, p0, 2);
            p1 += __shfl_xor_sync(0xffffffffu, p1, 1);
            p1 += __shfl_xor_sync(0xffffffffu, p1, 2);
            if (tg == 0) {
                int e0 = eW + g;
                if (e0 < E)     out[e0]     = softplus_f(p0 + b3v);
                if (e0 + 8 < E) out[e0 + 8] = softplus_f(p1 + b3v);
            }
        }
        // next iteration's __syncwarp orders A reuse; warp-private rows only
    }
}

// ===========================================================================
extern "C" void kernel_launch(void* const* d_in, const int* in_sizes, int n_in,
                              void* d_out, int out_size)
{
    const float* z     = (const float*)d_in[0];
    const void*  ei    = d_in[1];
    const void*  bt    = d_in[2];
    const float* embed = (const float*)d_in[3];
    const float* W1    = (const float*)d_in[4];
    const float* b1    = (const float*)d_in[5];
    const float* W2    = (const float*)d_in[6];
    const float* b2    = (const float*)d_in[7];
    const float* W3    = (const float*)d_in[8];
    const float* b3    = (const float*)d_in[9];
    float* out = (float*)d_out;

    int nNodes = in_sizes[0] / 128;
    int E = out_size;
    int nTiles  = (E + ETILE - 1) / ETILE;
    int nTilesN = (nNodes + 63) / 64;

    static int attr_done = 0;
    if (!attr_done) {
        cudaFuncSetAttribute(node_mma_kernel,
                             cudaFuncAttributeMaxDynamicSharedMemorySize, NODE_SMEM);
        cudaFuncSetAttribute(edge_mma_kernel,
                             cudaFuncAttributeMaxDynamicSharedMemorySize, EDGE_SMEM);
        attr_done = 1;
    }

    detect_dtype_kernel<<<1, 32>>>((const int*)ei, (const int*)bt);
    cemb_kernel<<<7, 256>>>(embed, W1, b1);

    node_mma_kernel<<<444, 256, NODE_SMEM>>>(z, W1, nNodes, nTilesN);

    int eg = nTiles < 444 ? nTiles : 444;
    edge_mma_kernel<<<eg, 256, EDGE_SMEM>>>(ei, bt, W2, b2, W3, b3, out, E, nTiles);
}

// round 17
// speedup vs baseline: 2.4827x; 1.0307x over previous
#include <cuda_runtime.h>
#include <cuda_bf16.h>
#include <cuda_fp16.h>
#include <math.h>
#include <stdint.h>

// ---------------------------------------------------------------------------
// BondLengthHead (all-fp16 tensor path):
//   P = z @ W1[0:128,:], Q = z @ W1[128:256,:]
//     node_mma_kernel: A = fp16(z), W = fp16(W1) single-term, 3 CTAs/SM
//     P/Q stored fp16
//   C = embed @ W1[256:288,:] + b1  (13x128, stored fp16)
//   edge kernel (warp-autonomous, m32/warp, ETILE=256, 2 CTAs/SM):
//     g = hmax2(P[src] + Q[dst] + C[bt], 0)   (half2-native)
//     D = A * fp16(W2)   (m16n8k16 HMMA, f32 acc)  -- W frags amortized over m32
//     out = softplus(relu(D + b2) . W3 + b3)
// NOTE: harness compiles via compute_103 (no 'a') -> no tcgen05/TMEM allowed.
// ---------------------------------------------------------------------------

#define MAXN 100000

__device__ __half g_PQh[(size_t)MAXN * 256];   // [node][0:128]=P, [128:256]=Q
__device__ __half g_Ch[13 * 128];
__device__ int    g_ei_is64;
__device__ int    g_bt_is64;

__device__ __forceinline__ uint32_t smem_u32(const void* p) {
    uint32_t a;
    asm("{ .reg .u64 t; cvta.to.shared.u64 t, %1; cvt.u32.u64 %0, t; }"
        : "=r"(a) : "l"(p));
    return a;
}

__device__ __forceinline__ void ldsm_x4(uint32_t* r, uint32_t addr) {
    asm volatile("ldmatrix.sync.aligned.m8n8.x4.shared.b16 {%0,%1,%2,%3}, [%4];"
                 : "=r"(r[0]), "=r"(r[1]), "=r"(r[2]), "=r"(r[3]) : "r"(addr));
}

__device__ __forceinline__ void mma_fp16(float* d, const uint32_t* a,
                                         uint32_t b0, uint32_t b1) {
    asm volatile("mma.sync.aligned.m16n8k16.row.col.f32.f16.f16.f32 "
                 "{%0,%1,%2,%3}, {%4,%5,%6,%7}, {%8,%9}, {%0,%1,%2,%3};"
                 : "+f"(d[0]), "+f"(d[1]), "+f"(d[2]), "+f"(d[3])
                 : "r"(a[0]), "r"(a[1]), "r"(a[2]), "r"(a[3]),
                   "r"(b0), "r"(b1));
}

__device__ __forceinline__ float softplus_f(float x) {
    return fmaxf(x, 0.0f) + log1pf(expf(-fabsf(x)));
}

// ===========================================================================
__global__ void detect_dtype_kernel(const int* __restrict__ ei,
                                    const int* __restrict__ bt) {
    if (threadIdx.x == 0 && blockIdx.x == 0) {
        int e64 = 1, b64 = 1;
        #pragma unroll 1
        for (int i = 0; i < 64; i++) if (ei[2 * i + 1] != 0) { e64 = 0; break; }
        #pragma unroll 1
        for (int i = 0; i < 64; i++) if (bt[2 * i + 1] != 0) { b64 = 0; break; }
        g_ei_is64 = e64;
        g_bt_is64 = b64;
    }
}

__global__ void cemb_kernel(const float* __restrict__ embed,
                            const float* __restrict__ W1,
                            const float* __restrict__ b1) {
    int idx = blockIdx.x * 256 + threadIdx.x;
    if (idx < 13 * 128) {
        int t = idx >> 7, j = idx & 127;
        float s = b1[j];
        #pragma unroll
        for (int k = 0; k < 32; k++)
            s = fmaf(embed[t * 32 + k], W1[(256 + k) * 128 + j], s);
        g_Ch[idx] = __float2half_rn(s);
    }
}

// ===========================================================================
// Node GEMM: A = fp16(z), W = fp16(W1) single-term, out fp16, 3 CTAs/SM
// (unchanged from R16 pass)
// ===========================================================================
#define NROWB 272
#define NOFF_A   0
#define NOFF_WHI (64 * NROWB)                    // 17408
#define NODE_SMEM (NOFF_WHI + 128 * NROWB)       // 52224

__global__ void __launch_bounds__(256, 3)
node_mma_kernel(const float* __restrict__ z,
                const float* __restrict__ W1,
                int nNodes, int nTilesN)
{
    extern __shared__ char sb[];
    const uint32_t base = smem_u32(sb);
    char* Ah  = sb + NOFF_A;
    char* Whi = sb + NOFF_WHI;

    const int tid  = threadIdx.x;
    const int wid  = tid >> 5;
    const int lane = tid & 31;
    const int g    = lane >> 2;
    const int tg   = lane & 3;

    const int halfStride = gridDim.x >> 1;
    const int half = (blockIdx.x >= halfStride) ? 1 : 0;
    const int t0   = blockIdx.x - half * halfStride;
    const int krow = half * 128;

    for (int i = tid; i < 128 * 128; i += 256) {
        int k = i >> 7, n = i & 127;
        uint32_t off = (uint32_t)n * NROWB + (uint32_t)k * 2;
        *(__half*)(Whi + off) = __float2half_rn(W1[(krow + k) * 128 + n]);
    }

    const uint32_t rowoff = (uint32_t)(((lane & 7) + ((lane & 8) ? 8 : 0)) * NROWB
                                       + ((lane & 16) ? 16 : 0));
    const int mt = wid & 3;
    const int ng = (wid >> 2) * 64;
    const uint32_t aB   = base + NOFF_A + (uint32_t)(mt * 16) * NROWB + rowoff;
    const uint32_t wHiB = base + NOFF_WHI + (uint32_t)ng * NROWB + rowoff;

    const float4* z4 = (const float4*)z;

    for (int t = t0; t < nTilesN; t += halfStride) {
        const int nb = t * 64;
        __syncthreads();

        #pragma unroll 2
        for (int idx = tid; idx < 64 * 32; idx += 256) {
            int e = idx >> 5, c = idx & 31;
            float4 v = make_float4(0.f, 0.f, 0.f, 0.f);
            if (nb + e < nNodes) v = z4[(size_t)(nb + e) * 32 + c];
            union { uint2 u; __half2 h[2]; } ph;
            ph.h[0] = __float22half2_rn(make_float2(v.x, v.y));
            ph.h[1] = __float22half2_rn(make_float2(v.z, v.w));
            uint32_t off = (uint32_t)e * NROWB + (uint32_t)c * 8;
            *(uint2*)(Ah + off) = ph.u;
        }
        __syncthreads();

        float D[8][4];
        #pragma unroll
        for (int i = 0; i < 8; i++)
            #pragma unroll
            for (int j = 0; j < 4; j++) D[i][j] = 0.f;

        #pragma unroll
        for (int ks = 0; ks < 8; ks++) {
            uint32_t ah[4];
            ldsm_x4(ah, aB + ks * 32);
            #pragma unroll
            for (int p = 0; p < 4; p++) {
                uint32_t bh[4];
                ldsm_x4(bh, wHiB + (uint32_t)(p * 16) * NROWB + ks * 32);
                mma_fp16(D[2 * p],     ah, bh[0], bh[2]);
                mma_fp16(D[2 * p + 1], ah, bh[1], bh[3]);
            }
        }

        {
            int node0 = nb + mt * 16 + g;
            int cbase = half * 128 + ng + tg * 2;
            if (node0 < nNodes) {
                __half* r = &g_PQh[(size_t)node0 * 256 + cbase];
                #pragma unroll
                for (int j = 0; j < 8; j++)
                    *(__half2*)(r + j * 8) =
                        __float22half2_rn(make_float2(D[j][0], D[j][1]));
            }
            int node1 = node0 + 8;
            if (node1 < nNodes) {
                __half* r = &g_PQh[(size_t)node1 * 256 + cbase];
                #pragma unroll
                for (int j = 0; j < 8; j++)
                    *(__half2*)(r + j * 8) =
                        __float22half2_rn(make_float2(D[j][2], D[j][3]));
            }
        }
    }
}

// ===========================================================================
// Edge kernel: 8 warps x 32 edges (ETILE=256), W frags amortized over m32,
// 2 CTAs/SM, warp-autonomous
// ===========================================================================
#define ETILE  256
#define ROWB   272
#define OFF_A    0
#define OFF_WHI  (OFF_A + 256 * ROWB)     // 69632
#define OFF_BW   (OFF_WHI + 64 * ROWB)    // 87040
#define EDGE_SMEM (OFF_BW + 32 * 16)      // 87552

__global__ void __launch_bounds__(256, 2)
edge_mma_kernel(const void*  __restrict__ eiv,
                const void*  __restrict__ btv,
                const float* __restrict__ W2,
                const float* __restrict__ b2,
                const float* __restrict__ W3,
                const float* __restrict__ b3,
                float* __restrict__ out,
                int E, int nTiles)
{
    extern __shared__ char sb[];
    const uint32_t base = smem_u32(sb);

    char*   Ah   = sb + OFF_A;
    char*   Whi  = sb + OFF_WHI;
    float4* sBW4 = (float4*)(sb + OFF_BW);   // [32]: (b2[2i],W3[2i],b2[2i+1],W3[2i+1])

    const int tid  = threadIdx.x;
    const int wid  = tid >> 5;
    const int lane = tid & 31;
    const int g    = lane >> 2;
    const int tg   = lane & 3;
    const int ei64 = g_ei_is64, bt64 = g_bt_is64;

    // ---- one-time staging: W2 fp16, packed b2/W3 ----
    if (tid < 32) {
        int n = tid * 2;
        sBW4[tid] = make_float4(b2[n], W3[n], b2[n + 1], W3[n + 1]);
    }
    for (int i = tid; i < 128 * 64; i += 256) {
        int k = i >> 6, n = i & 63;
        uint32_t off = (uint32_t)n * ROWB + (uint32_t)k * 2;
        *(__half*)(Whi + off) = __float2half_rn(W2[i]);
    }
    __syncthreads();

    const float b3v = __ldg(b3);

    const uint32_t rowoff = (uint32_t)(((lane & 7) + ((lane & 8) ? 8 : 0)) * ROWB
                                       + ((lane & 16) ? 16 : 0));
    // warp owns A rows wid*32 .. +31 (two m16 tiles)
    const uint32_t aBase0  = base + OFF_A + (uint32_t)(wid * 32) * ROWB + rowoff;
    const uint32_t aBase1  = aBase0 + 16u * ROWB;
    const uint32_t wHiBase = base + OFF_WHI + rowoff;

    const uint2* PQ2 = (const uint2*)g_PQh;   // node row = 64 uint2 (P 0..31, Q 32..63)
    const uint2* C2  = (const uint2*)g_Ch;    // 13 rows x 32 uint2

    for (int tile = blockIdx.x; tile < nTiles; tile += gridDim.x) {
        const int eW = tile * ETILE + wid * 32;   // this warp's 32 edges

        // ---- indices: lane e -> src/dst/bt of edge eW+lane ----
        int rs, rd, rb;
        {
            int e = eW + lane;
            bool valid = e < E;
            if (ei64) {
                const long long* p = (const long long*)eiv;
                rs = valid ? (int)p[e] : 0;
                rd = valid ? (int)p[(size_t)E + e] : 0;
            } else {
                const int* p = (const int*)eiv;
                rs = valid ? p[e] : 0;
                rd = valid ? p[(size_t)E + e] : 0;
            }
            rb = valid ? (bt64 ? (int)((const long long*)btv)[e]
                               : ((const int*)btv)[e]) : 0;
        }
        __syncwarp();

        // ---- gather + half2 add + relu -> fp16 A rows ----
        const __half2 zero2 = __float2half2_rn(0.f);
        #pragma unroll 8
        for (int i = 0; i < 32; i++) {
            int s = __shfl_sync(0xffffffffu, rs, i);
            int d = __shfl_sync(0xffffffffu, rd, i);
            int b = __shfl_sync(0xffffffffu, rb, i);
            uint2 pu = PQ2[(size_t)((uint32_t)s * 64u + lane)];
            uint2 qu = PQ2[(size_t)((uint32_t)d * 64u + 32u + lane)];
            uint2 cu = __ldg(&C2[b * 32 + lane]);
            union { uint2 u; __half2 h[2]; } ph;
            ph.h[0] = __hmax2(__hadd2(__hadd2(*(__half2*)&pu.x, *(__half2*)&qu.x),
                                      *(__half2*)&cu.x), zero2);
            ph.h[1] = __hmax2(__hadd2(__hadd2(*(__half2*)&pu.y, *(__half2*)&qu.y),
                                      *(__half2*)&cu.y), zero2);
            uint32_t off = (uint32_t)(wid * 32 + i) * ROWB + (uint32_t)lane * 8;
            *(uint2*)(Ah + off) = ph.u;
        }
        __syncwarp();

        // ---- layer 2 MMAs: 32 edges x 64 n, W frags shared across 2 m-tiles ----
        float D0[8][4], D1[8][4];
        #pragma unroll
        for (int i = 0; i < 8; i++)
            #pragma unroll
            for (int j = 0; j < 4; j++) { D0[i][j] = 0.f; D1[i][j] = 0.f; }

        #pragma unroll
        for (int ks = 0; ks < 8; ks++) {
            uint32_t ah0[4], ah1[4];
            ldsm_x4(ah0, aBase0 + ks * 32);
            ldsm_x4(ah1, aBase1 + ks * 32);
            #pragma unroll
            for (int p = 0; p < 4; p++) {
                uint32_t bh[4];
                ldsm_x4(bh, wHiBase + (uint32_t)(p * 16) * ROWB + ks * 32);
                mma_fp16(D0[2 * p],     ah0, bh[0], bh[2]);
                mma_fp16(D0[2 * p + 1], ah0, bh[1], bh[3]);
                mma_fp16(D1[2 * p],     ah1, bh[0], bh[2]);
                mma_fp16(D1[2 * p + 1], ah1, bh[1], bh[3]);
            }
        }

        // ---- layer 3 + softplus (float4-packed b2/W3), per m-tile ----
        #pragma unroll
        for (int mt = 0; mt < 2; mt++) {
            float (*D)[4] = (mt == 0) ? D0 : D1;
            float p0 = 0.f, p1 = 0.f;
            #pragma unroll
            for (int nt = 0; nt < 8; nt++) {
                float4 bw = sBW4[nt * 4 + tg];   // n = nt*8 + tg*2, n+1
                p0 = fmaf(fmaxf(D[nt][0] + bw.x, 0.f), bw.y, p0);
                p0 = fmaf(fmaxf(D[nt][1] + bw.z, 0.f), bw.w, p0);
                p1 = fmaf(fmaxf(D[nt][2] + bw.x, 0.f), bw.y, p1);
                p1 = fmaf(fmaxf(D[nt][3] + bw.z, 0.f), bw.w, p1);
            }
            p0 += __shfl_xor_sync(0xffffffffu, p0, 1);
            p0 += __shfl_xor_sync(0xffffffffu, p0, 2);
            p1 += __shfl_xor_sync(0xffffffffu, p1, 1);
            p1 += __shfl_xor_sync(0xffffffffu, p1, 2);
            if (tg == 0) {
                int e0 = eW + mt * 16 + g;
                if (e0 < E)     out[e0]     = softplus_f(p0 + b3v);
                if (e0 + 8 < E) out[e0 + 8] = softplus_f(p1 + b3v);
            }
        }
        // next iteration's __syncwarp orders A reuse; warp-private rows only
    }
}

// ===========================================================================
extern "C" void kernel_launch(void* const* d_in, const int* in_sizes, int n_in,
                              void* d_out, int out_size)
{
    const float* z     = (const float*)d_in[0];
    const void*  ei    = d_in[1];
    const void*  bt    = d_in[2];
    const float* embed = (const float*)d_in[3];
    const float* W1    = (const float*)d_in[4];
    const float* b1    = (const float*)d_in[5];
    const float* W2    = (const float*)d_in[6];
    const float* b2    = (const float*)d_in[7];
    const float* W3    = (const float*)d_in[8];
    const float* b3    = (const float*)d_in[9];
    float* out = (float*)d_out;

    int nNodes = in_sizes[0] / 128;
    int E = out_size;
    int nTiles  = (E + ETILE - 1) / ETILE;
    int nTilesN = (nNodes + 63) / 64;

    static int attr_done = 0;
    if (!attr_done) {
        cudaFuncSetAttribute(node_mma_kernel,
                             cudaFuncAttributeMaxDynamicSharedMemorySize, NODE_SMEM);
        cudaFuncSetAttribute(edge_mma_kernel,
                             cudaFuncAttributeMaxDynamicSharedMemorySize, EDGE_SMEM);
        attr_done = 1;
    }

    detect_dtype_kernel<<<1, 32>>>((const int*)ei, (const int*)bt);
    cemb_kernel<<<7, 256>>>(embed, W1, b1);

    node_mma_kernel<<<444, 256, NODE_SMEM>>>(z, W1, nNodes, nTilesN);

    int eg = nTiles < 296 ? nTiles : 296;
    edge_mma_kernel<<<eg, 256, EDGE_SMEM>>>(ei, bt, W2, b2, W3, b3, out, E, nTiles);
}